// round 10
// baseline (speedup 1.0000x reference)
#include <cuda_runtime.h>
#include <cuda_fp16.h>
#include <cstdint>

#define BB 4
#define SS 4096
#define DD 64
#define HH 4
#define HDD 16
#define BH (BB*HH)

typedef unsigned long long ull;

// q/k: f16, per-row 16 elements stored PERMUTED: pos(e) = 4*((e>>1)&3) + 2*(e>>3) + (e&1)
__device__ __half g_q[BH*SS*HDD];      // 2 MB, scaled by 0.25*log2(e)
__device__ __half g_k[BH*SS*HDD];      // 2 MB
__device__ float  g_v[BH*SS*HDD];      // 4 MB
__device__ __half g_vt[BH*HDD*SS];     // 2 MB, [bh*16+e][t], t permuted per 16-group
__device__ float  g_Zpart[2*BH*SS];    // 512 KB
__device__ float  g_att[2*BB*SS*DD];   // 8 MB attend partials (concat layout)
__device__ float  g_o[BB*SS*DD];       // 4 MB, holds exp(o)
__device__ float  g_Zop[1024*64];      // 256 KB per-block column partials
__device__ float  g_Zo[BB*DD];         // final column sums

// ---------------- helpers ----------------
__device__ __forceinline__ void mma16816(float* d,
    uint32_t a0, uint32_t a1, uint32_t a2, uint32_t a3,
    uint32_t b0, uint32_t b1)
{
    asm volatile("mma.sync.aligned.m16n8k16.row.col.f32.f16.f16.f32 "
        "{%0,%1,%2,%3}, {%4,%5,%6,%7}, {%8,%9}, {%0,%1,%2,%3};"
        : "+f"(d[0]), "+f"(d[1]), "+f"(d[2]), "+f"(d[3])
        : "r"(a0), "r"(a1), "r"(a2), "r"(a3), "r"(b0), "r"(b1));
}
__device__ __forceinline__ uint32_t ex2h2(float lo, float hi)
{
    uint32_t h, r;
    asm("cvt.rn.f16x2.f32 %0, %1, %2;" : "=r"(h) : "f"(hi), "f"(lo));
    asm("ex2.approx.f16x2 %0, %1;" : "=r"(r) : "r"(h));
    return r;
}
__device__ __forceinline__ float ex2f(float x) {
    float y; asm("ex2.approx.f32 %0, %1;" : "=f"(y) : "f"(x)); return y;
}
__device__ __forceinline__ ull ffma2(ull a, ull b, ull c) {
    ull d; asm("fma.rn.f32x2 %0, %1, %2, %3;" : "=l"(d) : "l"(a), "l"(b), "l"(c)); return d;
}
__device__ __forceinline__ float2 unpk(ull v) {
    float2 f; asm("mov.b64 {%0, %1}, %2;" : "=f"(f.x), "=f"(f.y) : "l"(v)); return f;
}
__device__ __forceinline__ int permpos(int e)
{
    return 4*((e>>1)&3) + 2*(e>>3) + (e&1);
}
__device__ __forceinline__ uint32_t smem_u32(const void* p) {
    uint32_t a; asm("{ .reg .u64 t; cvta.to.shared.u64 t, %1; cvt.u32.u64 %0, t; }" : "=r"(a) : "l"(p));
    return a;
}
__device__ __forceinline__ void cpa16(uint32_t s, const void* g) {
    asm volatile("cp.async.cg.shared.global [%0], [%1], 16;" :: "r"(s), "l"(g));
}
#define CP_COMMIT() asm volatile("cp.async.commit_group;")
#define CP_WAIT1()  asm volatile("cp.async.wait_group 1;")
#define CP_WAIT0()  asm volatile("cp.async.wait_group 0;")

// Fragment-order staging address for a 16-byte chunk (row r within 128-row tile, half-chunk c):
__device__ __forceinline__ uint32_t frag_dst(int r, int c) {
    return (uint32_t)((r>>4)*512 + ((r>>3)&1)*256 + (r&7)*32 + c*16);
}

// dot-64 over two float4 streams using packed ffma2
union f4u { float4 f; ull u[2]; };

// ---------------- K1: all three projections in one grid (y = which) ----------------
__global__ __launch_bounds__(256) void proj_kernel(
    const float* __restrict__ x,
    const float* __restrict__ Wq, const float* __restrict__ bq,
    const float* __restrict__ Wk, const float* __restrict__ bk,
    const float* __restrict__ Wv, const float* __restrict__ bv,
    float qscale)
{
    __shared__ float xs[16][64];
    __shared__ float wt[HH][HDD][68];
    int which = blockIdx.y;
    const float* W    = (which == 0) ? Wq : (which == 1) ? Wk : Wv;
    const float* bias = (which == 0) ? bq : (which == 1) ? bk : bv;
    float scale = (which == 0) ? qscale : 1.0f;

    int tid = threadIdx.x;
    int row0 = blockIdx.x * 16;

    for (int i = tid; i < HH*DD*HDD; i += 256) {
        int h = i >> 10, rem = i & 1023, d = rem >> 4, e = rem & 15;
        wt[h][e][d] = W[i];
    }
    for (int i = tid; i < 16*64; i += 256)
        xs[i>>6][i&63] = x[row0*64 + i];
    __syncthreads();

    int g = tid >> 6, h = (tid >> 4) & 3, e = tid & 15;
    float bval = bias[h*HDD + e];
    const float4* wrow = (const float4*)&wt[h][e][0];
    int pp = permpos(e);

    #pragma unroll
    for (int r = 0; r < 4; r++) {
        int sl = g + r*4;
        const float4* xrow = (const float4*)&xs[sl][0];
        ull ap = 0ULL, aq = 0ULL;
        #pragma unroll
        for (int j = 0; j < 16; j++) {
            f4u xv, wv;
            xv.f = xrow[j]; wv.f = wrow[j];
            ap = ffma2(xv.u[0], wv.u[0], ap);
            aq = ffma2(xv.u[1], wv.u[1], aq);
        }
        float2 p = unpk(ap), q = unpk(aq);
        float acc = (p.x + p.y) + (q.x + q.y);
        int bs = row0 + sl;
        int b = bs >> 12, s = bs & (SS-1);
        int base = ((b*HH + h)*SS + s)*HDD;
        float val = (acc + bval) * scale;
        if (which == 2)      g_v[base + e] = val;
        else if (which == 0) g_q[base + pp] = __float2half(val);
        else                 g_k[base + pp] = __float2half(val);
    }
}

// ---------------- Pass A: partial Z_t, q tiles staged; warp owns 32 t-rows ----------------
// grid (16, BH, 2), 256 thr.
__global__ __launch_bounds__(256) void colsumW_kernel()
{
    __shared__ __align__(16) __half sq[2][2048];   // 4 KB per buffer
    int tid = threadIdx.x, w = tid >> 5, lane = tid & 31;
    int bh = blockIdx.y, z = blockIdx.z;
    int trow = blockIdx.x * 256 + w * 32;
    const uint32_t ONE2 = 0x3C003C00u;

    const __half* kb = g_k + (size_t)bh*SS*HDD;
    int kg = lane >> 2, ktg = lane & 3;
    uint2 t0a = *((const uint2*)(kb + (trow +      kg)*HDD) + ktg);
    uint2 t0c = *((const uint2*)(kb + (trow +  8 + kg)*HDD) + ktg);
    uint2 t1a = *((const uint2*)(kb + (trow + 16 + kg)*HDD) + ktg);
    uint2 t1c = *((const uint2*)(kb + (trow + 24 + kg)*HDD) + ktg);
    uint32_t a0 = t0a.x, a2 = t0a.y, a1 = t0c.x, a3 = t0c.y;
    uint32_t b0 = t1a.x, b2 = t1a.y, b1 = t1c.x, b3 = t1c.y;

    const __half* qb = g_q + (size_t)bh*SS*HDD + (size_t)z*(SS/2)*HDD;

    int lr = tid >> 1, lc = tid & 1;
    uint32_t qdst = frag_dst(lr, lc);
    const __half* qsrc = qb + lr*HDD + lc*8;
    uint32_t sqb = smem_u32(sq);

    float zA[4] = {0,0,0,0}, zB[4] = {0,0,0,0};
    float zC[4] = {0,0,0,0}, zD[4] = {0,0,0,0};

    cpa16(sqb + qdst, qsrc);
    CP_COMMIT();

    const int NT = (SS/2)/128;   // 16 tiles
    for (int tile = 0; tile < NT; tile++) {
        int buf = tile & 1;
        if (tile + 1 < NT) {
            cpa16(sqb + (buf^1)*4096 + qdst, qsrc + (size_t)(tile+1)*128*HDD);
            CP_COMMIT();
            CP_WAIT1();
        } else {
            CP_WAIT0();
        }
        __syncthreads();
        const char* qp = (const char*)sq + buf*4096 + lane*8;
        #pragma unroll
        for (int st = 0; st < 8; st++) {
            uint2 q0 = *(const uint2*)(qp + st*512);
            uint2 q1 = *(const uint2*)(qp + st*512 + 256);
            float d0[4]={0,0,0,0}, d1[4]={0,0,0,0};
            mma16816(d0, a0,a1,a2,a3, q0.x, q0.y);
            mma16816(d1, a0,a1,a2,a3, q1.x, q1.y);
            uint32_t w0 = ex2h2(d0[0], d0[1]);
            uint32_t w1 = ex2h2(d0[2], d0[3]);
            uint32_t w2 = ex2h2(d1[0], d1[1]);
            uint32_t w3 = ex2h2(d1[2], d1[3]);
            mma16816((st & 1) ? zB : zA, w0,w1,w2,w3, ONE2, ONE2);
            float e0[4]={0,0,0,0}, e1[4]={0,0,0,0};
            mma16816(e0, b0,b1,b2,b3, q0.x, q0.y);
            mma16816(e1, b0,b1,b2,b3, q1.x, q1.y);
            uint32_t w4 = ex2h2(e0[0], e0[1]);
            uint32_t w5 = ex2h2(e0[2], e0[3]);
            uint32_t w6 = ex2h2(e1[0], e1[1]);
            uint32_t w7 = ex2h2(e1[2], e1[3]);
            mma16816((st & 1) ? zD : zC, w4,w5,w6,w7, ONE2, ONE2);
        }
        __syncthreads();
    }
    if (ktg == 0) {
        float* zp = g_Zpart + ((size_t)z*BH + bh)*SS + trow;
        zp[kg]      = zA[0] + zB[0];
        zp[8 + kg]  = zA[2] + zB[2];
        zp[16 + kg] = zC[0] + zD[0];
        zp[24 + kg] = zC[2] + zD[2];
    }
}

// ---------------- vnorm: vt[bh][e][t] = f16(v[bh][t][e] / Z_t), t-permuted ----------------
__global__ __launch_bounds__(256) void vnorm_kernel()
{
    int i = blockIdx.x * 256 + threadIdx.x;       // bh*SS + t
    float r = 1.0f / (g_Zpart[i] + g_Zpart[(size_t)BH*SS + i]);
    int bh = i >> 12, t = i & (SS-1);
    int tp = (t & ~15) + permpos(t & 15);
    const float4* vp = (const float4*)&g_v[(size_t)i*HDD];
    __half* dst = g_vt + (size_t)bh*HDD*SS + tp;
    #pragma unroll
    for (int j = 0; j < 4; j++) {
        float4 v = vp[j];
        dst[(size_t)(4*j+0)*SS] = __float2half(v.x * r);
        dst[(size_t)(4*j+1)*SS] = __float2half(v.y * r);
        dst[(size_t)(4*j+2)*SS] = __float2half(v.z * r);
        dst[(size_t)(4*j+3)*SS] = __float2half(v.w * r);
    }
}

// ---------------- Pass B: partial attended; warp owns 32 s-rows ----------------
// grid (16, BH, 2), 256 thr.
__global__ __launch_bounds__(256) void attendW_kernel()
{
    __shared__ __align__(16) __half sk[2][2048];
    __shared__ __align__(16) __half sv[2][2048];
    int tid = threadIdx.x, w = tid >> 5, lane = tid & 31;
    int bh = blockIdx.y, z = blockIdx.z;
    int srow = blockIdx.x * 256 + w * 32;

    const __half* qb = g_q + (size_t)bh*SS*HDD;
    int qg = lane >> 2, qtg = lane & 3;
    uint2 s0a = *((const uint2*)(qb + (srow +      qg)*HDD) + qtg);
    uint2 s0c = *((const uint2*)(qb + (srow +  8 + qg)*HDD) + qtg);
    uint2 s1a = *((const uint2*)(qb + (srow + 16 + qg)*HDD) + qtg);
    uint2 s1c = *((const uint2*)(qb + (srow + 24 + qg)*HDD) + qtg);
    uint32_t a0 = s0a.x, a2 = s0a.y, a1 = s0c.x, a3 = s0c.y;
    uint32_t b0 = s1a.x, b2 = s1a.y, b1 = s1c.x, b3 = s1c.y;

    const __half* kb = g_k + (size_t)bh*SS*HDD + (size_t)z*(SS/2)*HDD;
    const __half* vt = g_vt + (size_t)bh*HDD*SS + (size_t)z*(SS/2);

    int kr = tid >> 1, kc2 = tid & 1;
    uint32_t kdst = frag_dst(kr, kc2);
    const __half* ksrc = kb + kr*HDD + kc2*8;
    int ve = tid >> 4, vcv = tid & 15;
    uint32_t vdst = (uint32_t)((vcv>>1)*512 + (ve>>3)*256 + (ve&7)*32 + (vcv&1)*16);
    const __half* vsrc = vt + (size_t)ve*SS + vcv*8;

    uint32_t skb = smem_u32(sk), svb = smem_u32(sv);

    float o0[8] = {0,0,0,0,0,0,0,0};
    float o1[8] = {0,0,0,0,0,0,0,0};

    cpa16(skb + kdst, ksrc);
    cpa16(svb + vdst, vsrc);
    CP_COMMIT();

    const int NT = (SS/2)/128;
    for (int tile = 0; tile < NT; tile++) {
        int buf = tile & 1;
        if (tile + 1 < NT) {
            cpa16(skb + (buf^1)*4096 + kdst, ksrc + (size_t)(tile+1)*128*HDD);
            cpa16(svb + (buf^1)*4096 + vdst, vsrc + (size_t)(tile+1)*128);
            CP_COMMIT();
            CP_WAIT1();
        } else {
            CP_WAIT0();
        }
        __syncthreads();
        const char* kp = (const char*)sk + buf*4096 + lane*8;
        const char* vp = (const char*)sv + buf*4096 + lane*8;
        #pragma unroll
        for (int st = 0; st < 8; st++) {
            uint2 k0 = *(const uint2*)(kp + st*512);
            uint2 k1 = *(const uint2*)(kp + st*512 + 256);
            uint2 v0 = *(const uint2*)(vp + st*512);
            uint2 v1 = *(const uint2*)(vp + st*512 + 256);
            float d0[4] = {0,0,0,0}, d1[4] = {0,0,0,0};
            mma16816(d0, a0,a1,a2,a3, k0.x, k0.y);
            mma16816(d1, a0,a1,a2,a3, k1.x, k1.y);
            uint32_t w0 = ex2h2(d0[0], d0[1]);
            uint32_t w1 = ex2h2(d0[2], d0[3]);
            uint32_t w2 = ex2h2(d1[0], d1[1]);
            uint32_t w3 = ex2h2(d1[2], d1[3]);
            mma16816(o0,     w0,w1,w2,w3, v0.x, v0.y);
            mma16816(o0 + 4, w0,w1,w2,w3, v1.x, v1.y);
            float e0[4] = {0,0,0,0}, e1[4] = {0,0,0,0};
            mma16816(e0, b0,b1,b2,b3, k0.x, k0.y);
            mma16816(e1, b0,b1,b2,b3, k1.x, k1.y);
            uint32_t w4 = ex2h2(e0[0], e0[1]);
            uint32_t w5 = ex2h2(e0[2], e0[3]);
            uint32_t w6 = ex2h2(e1[0], e1[1]);
            uint32_t w7 = ex2h2(e1[2], e1[3]);
            mma16816(o1,     w4,w5,w6,w7, v0.x, v0.y);
            mma16816(o1 + 4, w4,w5,w6,w7, v1.x, v1.y);
        }
        __syncthreads();
    }

    int b = bh >> 2, h = bh & 3;
    float* att = g_att + (size_t)z*BB*SS*DD + (size_t)h*HDD;
    {
        float* dst0 = att + (size_t)(b*SS + srow + qg)*DD;
        float* dst1 = att + (size_t)(b*SS + srow + 8 + qg)*DD;
        *(float2*)(dst0 + 2*qtg)     = make_float2(o0[0], o0[1]);
        *(float2*)(dst1 + 2*qtg)     = make_float2(o0[2], o0[3]);
        *(float2*)(dst0 + 8 + 2*qtg) = make_float2(o0[4], o0[5]);
        *(float2*)(dst1 + 8 + 2*qtg) = make_float2(o0[6], o0[7]);
    }
    {
        float* dst0 = att + (size_t)(b*SS + srow + 16 + qg)*DD;
        float* dst1 = att + (size_t)(b*SS + srow + 24 + qg)*DD;
        *(float2*)(dst0 + 2*qtg)     = make_float2(o1[0], o1[1]);
        *(float2*)(dst1 + 2*qtg)     = make_float2(o1[2], o1[3]);
        *(float2*)(dst0 + 8 + 2*qtg) = make_float2(o1[4], o1[5]);
        *(float2*)(dst1 + 8 + 2*qtg) = make_float2(o1[6], o1[7]);
    }
}

// ---------------- out_proj: o = (att0+att1) @ Wo + bo, write exp(o), column partials ----------------
__global__ __launch_bounds__(256) void out_proj_kernel(
    const float* __restrict__ Wo, const float* __restrict__ bo)
{
    __shared__ float cs[16][64];
    __shared__ float wt[64][68];
    __shared__ float red[4][64];
    int tid = threadIdx.x;
    int row0 = blockIdx.x * 16;
    const float LOG2E = 1.4426950408889634f;

    for (int i = tid; i < 64*64; i += 256) {
        int c = i >> 6, d = i & 63;
        wt[d][c] = Wo[i];
    }
    for (int i = tid; i < 16*64; i += 256)
        cs[i>>6][i&63] = g_att[row0*64 + i] + g_att[(size_t)BB*SS*DD + row0*64 + i];
    __syncthreads();

    int d = tid & 63, r = tid >> 6;
    float bb = bo[d];
    const float4* wrow = (const float4*)&wt[d][0];
    float local = 0.f;

    #pragma unroll
    for (int rr = 0; rr < 4; rr++) {
        int row = r + rr*4;
        const float4* crow = (const float4*)&cs[row][0];
        ull ap = 0ULL, aq = 0ULL;
        #pragma unroll
        for (int j = 0; j < 16; j++) {
            f4u cv, wv;
            cv.f = crow[j]; wv.f = wrow[j];
            ap = ffma2(cv.u[0], wv.u[0], ap);
            aq = ffma2(cv.u[1], wv.u[1], aq);
        }
        float2 p = unpk(ap), q = unpk(aq);
        float acc = (p.x + p.y) + (q.x + q.y);
        float ev = ex2f((acc + bb) * LOG2E);    // shift-free: |o| <= ~3
        g_o[(row0 + row)*64 + d] = ev;
        local += ev;
    }
    red[r][d] = local;
    __syncthreads();
    if (r == 0)
        g_Zop[blockIdx.x*64 + d] = red[0][d] + red[1][d] + red[2][d] + red[3][d];
}

// ---------------- zsum: per-(b,d) column sums from 256 block partials ----------------
__global__ __launch_bounds__(256) void zsum_kernel()
{
    __shared__ float red[4][64];
    int b = blockIdx.x;
    int d = threadIdx.x & 63, cg = threadIdx.x >> 6;
    float s = 0.f;
    for (int c = cg; c < 256; c += 4)
        s += g_Zop[(b*256 + c)*64 + d];
    red[cg][d] = s;
    __syncthreads();
    if (cg == 0)
        g_Zo[b*64 + d] = red[0][d] + red[1][d] + red[2][d] + red[3][d];
}

// ---------------- final: out = exp(o) / Z ----------------
__global__ __launch_bounds__(256) void final_scale_kernel(float* __restrict__ out)
{
    int idx = blockIdx.x * 256 + threadIdx.x;     // float4 index, 262144 total
    int row = idx >> 4;
    int b = row >> 12;
    int d4 = idx & 15;
    float4 e = ((const float4*)g_o)[idx];
    float4 zz = ((const float4*)g_Zo)[b*16 + d4];
    float4 o;
    o.x = __fdividef(e.x, zz.x);
    o.y = __fdividef(e.y, zz.y);
    o.z = __fdividef(e.z, zz.z);
    o.w = __fdividef(e.w, zz.w);
    ((float4*)out)[idx] = o;
}

// ---------------- launch ----------------
extern "C" void kernel_launch(void* const* d_in, const int* in_sizes, int n_in,
                              void* d_out, int out_size)
{
    const float* x  = (const float*)d_in[0];
    const float* Wq = (const float*)d_in[1];
    const float* bq = (const float*)d_in[2];
    const float* Wk = (const float*)d_in[3];
    const float* bk = (const float*)d_in[4];
    const float* Wv = (const float*)d_in[5];
    const float* bv = (const float*)d_in[6];
    const float* Wo = (const float*)d_in[7];
    const float* bo = (const float*)d_in[8];
    float* out = (float*)d_out;

    const float qscale = 0.25f * 1.4426950408889634f;  // 1/sqrt(HD) * log2(e)

    proj_kernel<<<dim3(BB*SS/16, 3), 256>>>(x, Wq, bq, Wk, bk, Wv, bv, qscale);

    colsumW_kernel<<<dim3(16, BH, 2), 256>>>();
    vnorm_kernel<<<(BH*SS)/256, 256>>>();
    attendW_kernel<<<dim3(16, BH, 2), 256>>>();

    out_proj_kernel<<<BB*SS/16, 256>>>(Wo, bo);
    zsum_kernel<<<BB, 256>>>();
    final_scale_kernel<<<(BB*SS*DD/4)/256, 256>>>(out);
}

// round 11
// speedup vs baseline: 1.0551x; 1.0551x over previous
#include <cuda_runtime.h>
#include <cuda_fp16.h>
#include <cstdint>

#define BB 4
#define SS 4096
#define DD 64
#define HH 4
#define HDD 16
#define BH (BB*HH)

typedef unsigned long long ull;

// q/k: f16, per-row 16 elements stored PERMUTED: pos(e) = 4*((e>>1)&3) + 2*(e>>3) + (e&1)
__device__ __half g_q[BH*SS*HDD];      // 2 MB, scaled by 0.25*log2(e)
__device__ __half g_k[BH*SS*HDD];      // 2 MB
__device__ float  g_v[BH*SS*HDD];      // 4 MB
__device__ __half g_vt[BH*HDD*SS];     // 2 MB, [bh*16+e][t], t permuted per 16-group
__device__ float  g_Zpart[2*BH*SS];    // 512 KB
__device__ float  g_att[2*BB*SS*DD];   // 8 MB attend partials (concat layout)
__device__ float  g_o[BB*SS*DD];       // 4 MB, holds exp(o)
__device__ float  g_Zop[1024*64];      // 256 KB per-block column partials
__device__ float  g_Zo[BB*DD];         // final column sums

// ---------------- helpers ----------------
__device__ __forceinline__ void mma16816(float* d,
    uint32_t a0, uint32_t a1, uint32_t a2, uint32_t a3,
    uint32_t b0, uint32_t b1)
{
    asm volatile("mma.sync.aligned.m16n8k16.row.col.f32.f16.f16.f32 "
        "{%0,%1,%2,%3}, {%4,%5,%6,%7}, {%8,%9}, {%0,%1,%2,%3};"
        : "+f"(d[0]), "+f"(d[1]), "+f"(d[2]), "+f"(d[3])
        : "r"(a0), "r"(a1), "r"(a2), "r"(a3), "r"(b0), "r"(b1));
}
__device__ __forceinline__ uint32_t ex2h2(float lo, float hi)
{
    uint32_t h, r;
    asm("cvt.rn.f16x2.f32 %0, %1, %2;" : "=r"(h) : "f"(hi), "f"(lo));
    asm("ex2.approx.f16x2 %0, %1;" : "=r"(r) : "r"(h));
    return r;
}
__device__ __forceinline__ float ex2f(float x) {
    float y; asm("ex2.approx.f32 %0, %1;" : "=f"(y) : "f"(x)); return y;
}
__device__ __forceinline__ ull ffma2(ull a, ull b, ull c) {
    ull d; asm("fma.rn.f32x2 %0, %1, %2, %3;" : "=l"(d) : "l"(a), "l"(b), "l"(c)); return d;
}
__device__ __forceinline__ float2 unpk(ull v) {
    float2 f; asm("mov.b64 {%0, %1}, %2;" : "=f"(f.x), "=f"(f.y) : "l"(v)); return f;
}
__device__ __forceinline__ int permpos(int e)
{
    return 4*((e>>1)&3) + 2*(e>>3) + (e&1);
}
__device__ __forceinline__ uint32_t smem_u32(const void* p) {
    uint32_t a; asm("{ .reg .u64 t; cvta.to.shared.u64 t, %1; cvt.u32.u64 %0, t; }" : "=r"(a) : "l"(p));
    return a;
}
__device__ __forceinline__ void cpa16(uint32_t s, const void* g) {
    asm volatile("cp.async.cg.shared.global [%0], [%1], 16;" :: "r"(s), "l"(g));
}
#define CP_COMMIT() asm volatile("cp.async.commit_group;")
#define CP_WAIT1()  asm volatile("cp.async.wait_group 1;")
#define CP_WAIT0()  asm volatile("cp.async.wait_group 0;")

// Fragment-order staging address for a 16-byte chunk (row r within 128-row tile, half-chunk c):
__device__ __forceinline__ uint32_t frag_dst(int r, int c) {
    return (uint32_t)((r>>4)*512 + ((r>>3)&1)*256 + (r&7)*32 + c*16);
}

// dot-64 over two float4 streams using packed ffma2
union f4u { float4 f; ull u[2]; };

// ---------------- K1: all three projections in one grid (y = which) ----------------
__global__ __launch_bounds__(256) void proj_kernel(
    const float* __restrict__ x,
    const float* __restrict__ Wq, const float* __restrict__ bq,
    const float* __restrict__ Wk, const float* __restrict__ bk,
    const float* __restrict__ Wv, const float* __restrict__ bv,
    float qscale)
{
    __shared__ float xs[16][64];
    __shared__ float wt[HH][HDD][68];
    int which = blockIdx.y;
    const float* W    = (which == 0) ? Wq : (which == 1) ? Wk : Wv;
    const float* bias = (which == 0) ? bq : (which == 1) ? bk : bv;
    float scale = (which == 0) ? qscale : 1.0f;

    int tid = threadIdx.x;
    int row0 = blockIdx.x * 16;

    for (int i = tid; i < HH*DD*HDD; i += 256) {
        int h = i >> 10, rem = i & 1023, d = rem >> 4, e = rem & 15;
        wt[h][e][d] = W[i];
    }
    for (int i = tid; i < 16*64; i += 256)
        xs[i>>6][i&63] = x[row0*64 + i];
    __syncthreads();

    int g = tid >> 6, h = (tid >> 4) & 3, e = tid & 15;
    float bval = bias[h*HDD + e];
    const float4* wrow = (const float4*)&wt[h][e][0];
    int pp = permpos(e);

    #pragma unroll
    for (int r = 0; r < 4; r++) {
        int sl = g + r*4;
        const float4* xrow = (const float4*)&xs[sl][0];
        ull ap = 0ULL, aq = 0ULL;
        #pragma unroll
        for (int j = 0; j < 16; j++) {
            f4u xv, wv;
            xv.f = xrow[j]; wv.f = wrow[j];
            ap = ffma2(xv.u[0], wv.u[0], ap);
            aq = ffma2(xv.u[1], wv.u[1], aq);
        }
        float2 p = unpk(ap), q = unpk(aq);
        float acc = (p.x + p.y) + (q.x + q.y);
        int bs = row0 + sl;
        int b = bs >> 12, s = bs & (SS-1);
        int base = ((b*HH + h)*SS + s)*HDD;
        float val = (acc + bval) * scale;
        if (which == 2)      g_v[base + e] = val;
        else if (which == 0) g_q[base + pp] = __float2half(val);
        else                 g_k[base + pp] = __float2half(val);
    }
}

// ---------------- Pass A: partial Z_t; 128-thr blocks, warp owns 32 t-rows ----------------
// grid (32, BH, 2), 128 thr.
__global__ __launch_bounds__(128, 7) void colsumW_kernel()
{
    __shared__ __align__(16) __half sq[2][2048];   // 4 KB per buffer
    int tid = threadIdx.x, w = tid >> 5, lane = tid & 31;
    int bh = blockIdx.y, z = blockIdx.z;
    int trow = blockIdx.x * 128 + w * 32;
    const uint32_t ONE2 = 0x3C003C00u;

    const __half* kb = g_k + (size_t)bh*SS*HDD;
    int kg = lane >> 2, ktg = lane & 3;
    uint2 t0a = *((const uint2*)(kb + (trow +      kg)*HDD) + ktg);
    uint2 t0c = *((const uint2*)(kb + (trow +  8 + kg)*HDD) + ktg);
    uint2 t1a = *((const uint2*)(kb + (trow + 16 + kg)*HDD) + ktg);
    uint2 t1c = *((const uint2*)(kb + (trow + 24 + kg)*HDD) + ktg);
    uint32_t a0 = t0a.x, a2 = t0a.y, a1 = t0c.x, a3 = t0c.y;
    uint32_t b0 = t1a.x, b2 = t1a.y, b1 = t1c.x, b3 = t1c.y;

    const __half* qb = g_q + (size_t)bh*SS*HDD + (size_t)z*(SS/2)*HDD;

    // loader: 256 chunks over 128 threads -> 2 chunks each
    int lr0 = tid >> 1, lc0 = tid & 1;
    uint32_t qdst0 = frag_dst(lr0, lc0);
    uint32_t qdst1 = frag_dst(lr0 + 64, lc0);
    const __half* qsrc0 = qb + lr0*HDD + lc0*8;
    const __half* qsrc1 = qb + (lr0 + 64)*HDD + lc0*8;
    uint32_t sqb = smem_u32(sq);

    float zA[4] = {0,0,0,0}, zB[4] = {0,0,0,0};
    float zC[4] = {0,0,0,0}, zD[4] = {0,0,0,0};

    cpa16(sqb + qdst0, qsrc0);
    cpa16(sqb + qdst1, qsrc1);
    CP_COMMIT();

    const int NT = (SS/2)/128;   // 16 tiles
    for (int tile = 0; tile < NT; tile++) {
        int buf = tile & 1;
        if (tile + 1 < NT) {
            size_t off = (size_t)(tile+1)*128*HDD;
            cpa16(sqb + (buf^1)*4096 + qdst0, qsrc0 + off);
            cpa16(sqb + (buf^1)*4096 + qdst1, qsrc1 + off);
            CP_COMMIT();
            CP_WAIT1();
        } else {
            CP_WAIT0();
        }
        __syncthreads();
        const char* qp = (const char*)sq + buf*4096 + lane*8;
        #pragma unroll
        for (int st = 0; st < 8; st++) {
            uint2 q0 = *(const uint2*)(qp + st*512);
            uint2 q1 = *(const uint2*)(qp + st*512 + 256);
            float d0[4]={0,0,0,0}, d1[4]={0,0,0,0};
            mma16816(d0, a0,a1,a2,a3, q0.x, q0.y);
            mma16816(d1, a0,a1,a2,a3, q1.x, q1.y);
            uint32_t w0 = ex2h2(d0[0], d0[1]);
            uint32_t w1 = ex2h2(d0[2], d0[3]);
            uint32_t w2 = ex2h2(d1[0], d1[1]);
            uint32_t w3 = ex2h2(d1[2], d1[3]);
            mma16816((st & 1) ? zB : zA, w0,w1,w2,w3, ONE2, ONE2);
            float e0[4]={0,0,0,0}, e1[4]={0,0,0,0};
            mma16816(e0, b0,b1,b2,b3, q0.x, q0.y);
            mma16816(e1, b0,b1,b2,b3, q1.x, q1.y);
            uint32_t w4 = ex2h2(e0[0], e0[1]);
            uint32_t w5 = ex2h2(e0[2], e0[3]);
            uint32_t w6 = ex2h2(e1[0], e1[1]);
            uint32_t w7 = ex2h2(e1[2], e1[3]);
            mma16816((st & 1) ? zD : zC, w4,w5,w6,w7, ONE2, ONE2);
        }
        __syncthreads();
    }
    if (ktg == 0) {
        float* zp = g_Zpart + ((size_t)z*BH + bh)*SS + trow;
        zp[kg]      = zA[0] + zB[0];
        zp[8 + kg]  = zA[2] + zB[2];
        zp[16 + kg] = zC[0] + zD[0];
        zp[24 + kg] = zC[2] + zD[2];
    }
}

// ---------------- vnorm: vt[bh][e][t] = f16(v[bh][t][e] / Z_t), t-permuted ----------------
__global__ __launch_bounds__(256) void vnorm_kernel()
{
    int i = blockIdx.x * 256 + threadIdx.x;       // bh*SS + t
    float r = 1.0f / (g_Zpart[i] + g_Zpart[(size_t)BH*SS + i]);
    int bh = i >> 12, t = i & (SS-1);
    int tp = (t & ~15) + permpos(t & 15);
    const float4* vp = (const float4*)&g_v[(size_t)i*HDD];
    __half* dst = g_vt + (size_t)bh*HDD*SS + tp;
    #pragma unroll
    for (int j = 0; j < 4; j++) {
        float4 v = vp[j];
        dst[(size_t)(4*j+0)*SS] = __float2half(v.x * r);
        dst[(size_t)(4*j+1)*SS] = __float2half(v.y * r);
        dst[(size_t)(4*j+2)*SS] = __float2half(v.z * r);
        dst[(size_t)(4*j+3)*SS] = __float2half(v.w * r);
    }
}

// ---------------- Pass B: partial attended; 128-thr blocks, warp owns 32 s-rows ----------------
// grid (32, BH, 2), 128 thr.
__global__ __launch_bounds__(128, 7) void attendW_kernel()
{
    __shared__ __align__(16) __half sk[2][2048];
    __shared__ __align__(16) __half sv[2][2048];
    int tid = threadIdx.x, w = tid >> 5, lane = tid & 31;
    int bh = blockIdx.y, z = blockIdx.z;
    int srow = blockIdx.x * 128 + w * 32;

    const __half* qb = g_q + (size_t)bh*SS*HDD;
    int qg = lane >> 2, qtg = lane & 3;
    uint2 s0a = *((const uint2*)(qb + (srow +      qg)*HDD) + qtg);
    uint2 s0c = *((const uint2*)(qb + (srow +  8 + qg)*HDD) + qtg);
    uint2 s1a = *((const uint2*)(qb + (srow + 16 + qg)*HDD) + qtg);
    uint2 s1c = *((const uint2*)(qb + (srow + 24 + qg)*HDD) + qtg);
    uint32_t a0 = s0a.x, a2 = s0a.y, a1 = s0c.x, a3 = s0c.y;
    uint32_t b0 = s1a.x, b2 = s1a.y, b1 = s1c.x, b3 = s1c.y;

    const __half* kb = g_k + (size_t)bh*SS*HDD + (size_t)z*(SS/2)*HDD;
    const __half* vt = g_vt + (size_t)bh*HDD*SS + (size_t)z*(SS/2);

    // loaders: 256 chunks each over 128 threads -> 2 chunks each
    int kr0 = tid >> 1, kc0 = tid & 1;
    uint32_t kdst0 = frag_dst(kr0, kc0);
    uint32_t kdst1 = frag_dst(kr0 + 64, kc0);
    const __half* ksrc0 = kb + kr0*HDD + kc0*8;
    const __half* ksrc1 = kb + (kr0 + 64)*HDD + kc0*8;

    int ve0 = tid >> 4, vcv0 = tid & 15;
    int ve1 = (tid + 128) >> 4, vcv1 = tid & 15;
    uint32_t vdst0 = (uint32_t)((vcv0>>1)*512 + (ve0>>3)*256 + (ve0&7)*32 + (vcv0&1)*16);
    uint32_t vdst1 = (uint32_t)((vcv1>>1)*512 + (ve1>>3)*256 + (ve1&7)*32 + (vcv1&1)*16);
    const __half* vsrc0 = vt + (size_t)ve0*SS + vcv0*8;
    const __half* vsrc1 = vt + (size_t)ve1*SS + vcv1*8;

    uint32_t skb = smem_u32(sk), svb = smem_u32(sv);

    float o0[8] = {0,0,0,0,0,0,0,0};
    float o1[8] = {0,0,0,0,0,0,0,0};

    cpa16(skb + kdst0, ksrc0);
    cpa16(skb + kdst1, ksrc1);
    cpa16(svb + vdst0, vsrc0);
    cpa16(svb + vdst1, vsrc1);
    CP_COMMIT();

    const int NT = (SS/2)/128;
    for (int tile = 0; tile < NT; tile++) {
        int buf = tile & 1;
        if (tile + 1 < NT) {
            size_t koff = (size_t)(tile+1)*128*HDD;
            cpa16(skb + (buf^1)*4096 + kdst0, ksrc0 + koff);
            cpa16(skb + (buf^1)*4096 + kdst1, ksrc1 + koff);
            cpa16(svb + (buf^1)*4096 + vdst0, vsrc0 + (size_t)(tile+1)*128);
            cpa16(svb + (buf^1)*4096 + vdst1, vsrc1 + (size_t)(tile+1)*128);
            CP_COMMIT();
            CP_WAIT1();
        } else {
            CP_WAIT0();
        }
        __syncthreads();
        const char* kp = (const char*)sk + buf*4096 + lane*8;
        const char* vp = (const char*)sv + buf*4096 + lane*8;
        #pragma unroll
        for (int st = 0; st < 8; st++) {
            uint2 k0 = *(const uint2*)(kp + st*512);
            uint2 k1 = *(const uint2*)(kp + st*512 + 256);
            uint2 v0 = *(const uint2*)(vp + st*512);
            uint2 v1 = *(const uint2*)(vp + st*512 + 256);
            float d0[4] = {0,0,0,0}, d1[4] = {0,0,0,0};
            mma16816(d0, a0,a1,a2,a3, k0.x, k0.y);
            mma16816(d1, a0,a1,a2,a3, k1.x, k1.y);
            uint32_t w0 = ex2h2(d0[0], d0[1]);
            uint32_t w1 = ex2h2(d0[2], d0[3]);
            uint32_t w2 = ex2h2(d1[0], d1[1]);
            uint32_t w3 = ex2h2(d1[2], d1[3]);
            mma16816(o0,     w0,w1,w2,w3, v0.x, v0.y);
            mma16816(o0 + 4, w0,w1,w2,w3, v1.x, v1.y);
            float e0[4] = {0,0,0,0}, e1[4] = {0,0,0,0};
            mma16816(e0, b0,b1,b2,b3, k0.x, k0.y);
            mma16816(e1, b0,b1,b2,b3, k1.x, k1.y);
            uint32_t w4 = ex2h2(e0[0], e0[1]);
            uint32_t w5 = ex2h2(e0[2], e0[3]);
            uint32_t w6 = ex2h2(e1[0], e1[1]);
            uint32_t w7 = ex2h2(e1[2], e1[3]);
            mma16816(o1,     w4,w5,w6,w7, v0.x, v0.y);
            mma16816(o1 + 4, w4,w5,w6,w7, v1.x, v1.y);
        }
        __syncthreads();
    }

    int b = bh >> 2, h = bh & 3;
    float* att = g_att + (size_t)z*BB*SS*DD + (size_t)h*HDD;
    {
        float* dst0 = att + (size_t)(b*SS + srow + qg)*DD;
        float* dst1 = att + (size_t)(b*SS + srow + 8 + qg)*DD;
        *(float2*)(dst0 + 2*qtg)     = make_float2(o0[0], o0[1]);
        *(float2*)(dst1 + 2*qtg)     = make_float2(o0[2], o0[3]);
        *(float2*)(dst0 + 8 + 2*qtg) = make_float2(o0[4], o0[5]);
        *(float2*)(dst1 + 8 + 2*qtg) = make_float2(o0[6], o0[7]);
    }
    {
        float* dst0 = att + (size_t)(b*SS + srow + 16 + qg)*DD;
        float* dst1 = att + (size_t)(b*SS + srow + 24 + qg)*DD;
        *(float2*)(dst0 + 2*qtg)     = make_float2(o1[0], o1[1]);
        *(float2*)(dst1 + 2*qtg)     = make_float2(o1[2], o1[3]);
        *(float2*)(dst0 + 8 + 2*qtg) = make_float2(o1[4], o1[5]);
        *(float2*)(dst1 + 8 + 2*qtg) = make_float2(o1[6], o1[7]);
    }
}

// ---------------- out_proj: o = (att0+att1) @ Wo + bo, write exp(o), column partials ----------------
__global__ __launch_bounds__(256) void out_proj_kernel(
    const float* __restrict__ Wo, const float* __restrict__ bo)
{
    __shared__ float cs[16][64];
    __shared__ float wt[64][68];
    __shared__ float red[4][64];
    int tid = threadIdx.x;
    int row0 = blockIdx.x * 16;
    const float LOG2E = 1.4426950408889634f;

    for (int i = tid; i < 64*64; i += 256) {
        int c = i >> 6, d = i & 63;
        wt[d][c] = Wo[i];
    }
    for (int i = tid; i < 16*64; i += 256)
        cs[i>>6][i&63] = g_att[row0*64 + i] + g_att[(size_t)BB*SS*DD + row0*64 + i];
    __syncthreads();

    int d = tid & 63, r = tid >> 6;
    float bb = bo[d];
    const float4* wrow = (const float4*)&wt[d][0];
    float local = 0.f;

    #pragma unroll
    for (int rr = 0; rr < 4; rr++) {
        int row = r + rr*4;
        const float4* crow = (const float4*)&cs[row][0];
        ull ap = 0ULL, aq = 0ULL;
        #pragma unroll
        for (int j = 0; j < 16; j++) {
            f4u cv, wv;
            cv.f = crow[j]; wv.f = wrow[j];
            ap = ffma2(cv.u[0], wv.u[0], ap);
            aq = ffma2(cv.u[1], wv.u[1], aq);
        }
        float2 p = unpk(ap), q = unpk(aq);
        float acc = (p.x + p.y) + (q.x + q.y);
        float ev = ex2f((acc + bb) * LOG2E);    // shift-free: |o| <= ~3
        g_o[(row0 + row)*64 + d] = ev;
        local += ev;
    }
    red[r][d] = local;
    __syncthreads();
    if (r == 0)
        g_Zop[blockIdx.x*64 + d] = red[0][d] + red[1][d] + red[2][d] + red[3][d];
}

// ---------------- zsum: per-(b,d) column sums from 256 block partials ----------------
__global__ __launch_bounds__(256) void zsum_kernel()
{
    __shared__ float red[4][64];
    int b = blockIdx.x;
    int d = threadIdx.x & 63, cg = threadIdx.x >> 6;
    float s = 0.f;
    for (int c = cg; c < 256; c += 4)
        s += g_Zop[(b*256 + c)*64 + d];
    red[cg][d] = s;
    __syncthreads();
    if (cg == 0)
        g_Zo[b*64 + d] = red[0][d] + red[1][d] + red[2][d] + red[3][d];
}

// ---------------- final: out = exp(o) / Z ----------------
__global__ __launch_bounds__(256) void final_scale_kernel(float* __restrict__ out)
{
    int idx = blockIdx.x * 256 + threadIdx.x;     // float4 index, 262144 total
    int row = idx >> 4;
    int b = row >> 12;
    int d4 = idx & 15;
    float4 e = ((const float4*)g_o)[idx];
    float4 zz = ((const float4*)g_Zo)[b*16 + d4];
    float4 o;
    o.x = __fdividef(e.x, zz.x);
    o.y = __fdividef(e.y, zz.y);
    o.z = __fdividef(e.z, zz.z);
    o.w = __fdividef(e.w, zz.w);
    ((float4*)out)[idx] = o;
}

// ---------------- launch ----------------
extern "C" void kernel_launch(void* const* d_in, const int* in_sizes, int n_in,
                              void* d_out, int out_size)
{
    const float* x  = (const float*)d_in[0];
    const float* Wq = (const float*)d_in[1];
    const float* bq = (const float*)d_in[2];
    const float* Wk = (const float*)d_in[3];
    const float* bk = (const float*)d_in[4];
    const float* Wv = (const float*)d_in[5];
    const float* bv = (const float*)d_in[6];
    const float* Wo = (const float*)d_in[7];
    const float* bo = (const float*)d_in[8];
    float* out = (float*)d_out;

    const float qscale = 0.25f * 1.4426950408889634f;  // 1/sqrt(HD) * log2(e)

    proj_kernel<<<dim3(BB*SS/16, 3), 256>>>(x, Wq, bq, Wk, bk, Wv, bv, qscale);

    colsumW_kernel<<<dim3(32, BH, 2), 128>>>();
    vnorm_kernel<<<(BH*SS)/256, 256>>>();
    attendW_kernel<<<dim3(32, BH, 2), 128>>>();

    out_proj_kernel<<<BB*SS/16, 256>>>(Wo, bo);
    zsum_kernel<<<BB, 256>>>();
    final_scale_kernel<<<(BB*SS*DD/4)/256, 256>>>(out);
}

// round 12
// speedup vs baseline: 1.3409x; 1.2709x over previous
#include <cuda_runtime.h>
#include <cuda_fp16.h>
#include <cstdint>

#define BB 4
#define SS 4096
#define DD 64
#define HH 4
#define HDD 16
#define BH (BB*HH)

typedef unsigned long long ull;

// q/k: f16, per-row 16 elements stored PERMUTED: pos(e) = 4*((e>>1)&3) + 2*(e>>3) + (e&1)
__device__ __half g_q[BH*SS*HDD];      // 2 MB, scaled by 0.25*log2(e)
__device__ __half g_k[BH*SS*HDD];      // 2 MB
__device__ float  g_v[BH*SS*HDD];      // 4 MB
__device__ __half g_vt[BH*HDD*SS];     // 2 MB, [bh*16+e][t], t permuted per 16-group
__device__ __half g_wt16[192*64];      // 24 KB: [which*64+h*16+e][d permuted], B-frag-ready
__device__ float  g_Zpart[2*BH*SS];    // 512 KB
__device__ float  g_att[2*BB*SS*DD];   // 8 MB attend partials (concat layout)
__device__ float  g_o[BB*SS*DD];       // 4 MB, holds exp(o)
__device__ float  g_Zop[1024*64];      // 256 KB per-block column partials
__device__ float  g_Zo[BB*DD];         // final column sums

// ---------------- helpers ----------------
__device__ __forceinline__ void mma16816(float* d,
    uint32_t a0, uint32_t a1, uint32_t a2, uint32_t a3,
    uint32_t b0, uint32_t b1)
{
    asm volatile("mma.sync.aligned.m16n8k16.row.col.f32.f16.f16.f32 "
        "{%0,%1,%2,%3}, {%4,%5,%6,%7}, {%8,%9}, {%0,%1,%2,%3};"
        : "+f"(d[0]), "+f"(d[1]), "+f"(d[2]), "+f"(d[3])
        : "r"(a0), "r"(a1), "r"(a2), "r"(a3), "r"(b0), "r"(b1));
}
__device__ __forceinline__ uint32_t ex2h2(float lo, float hi)
{
    uint32_t h, r;
    asm("cvt.rn.f16x2.f32 %0, %1, %2;" : "=r"(h) : "f"(hi), "f"(lo));
    asm("ex2.approx.f16x2 %0, %1;" : "=r"(r) : "r"(h));
    return r;
}
__device__ __forceinline__ uint32_t pkh2(float lo, float hi)
{
    uint32_t h;
    asm("cvt.rn.f16x2.f32 %0, %1, %2;" : "=r"(h) : "f"(hi), "f"(lo));
    return h;
}
__device__ __forceinline__ float ex2f(float x) {
    float y; asm("ex2.approx.f32 %0, %1;" : "=f"(y) : "f"(x)); return y;
}
__device__ __forceinline__ ull ffma2(ull a, ull b, ull c) {
    ull d; asm("fma.rn.f32x2 %0, %1, %2, %3;" : "=l"(d) : "l"(a), "l"(b), "l"(c)); return d;
}
__device__ __forceinline__ float2 unpk(ull v) {
    float2 f; asm("mov.b64 {%0, %1}, %2;" : "=f"(f.x), "=f"(f.y) : "l"(v)); return f;
}
__device__ __forceinline__ int permpos(int e)
{
    return 4*((e>>1)&3) + 2*(e>>3) + (e&1);
}
__device__ __forceinline__ uint32_t smem_u32(const void* p) {
    uint32_t a; asm("{ .reg .u64 t; cvta.to.shared.u64 t, %1; cvt.u32.u64 %0, t; }" : "=r"(a) : "l"(p));
    return a;
}
__device__ __forceinline__ void cpa16(uint32_t s, const void* g) {
    asm volatile("cp.async.cg.shared.global [%0], [%1], 16;" :: "r"(s), "l"(g));
}
#define CP_COMMIT() asm volatile("cp.async.commit_group;")
#define CP_WAIT1()  asm volatile("cp.async.wait_group 1;")
#define CP_WAIT0()  asm volatile("cp.async.wait_group 0;")

__device__ __forceinline__ uint32_t frag_dst(int r, int c) {
    return (uint32_t)((r>>4)*512 + ((r>>3)&1)*256 + (r&7)*32 + c*16);
}
__device__ __forceinline__ void sts128(uint32_t a, uint32_t x, uint32_t y, uint32_t z, uint32_t w) {
    asm volatile("st.shared.v4.b32 [%0], {%1,%2,%3,%4};" :: "r"(a), "r"(x), "r"(y), "r"(z), "r"(w) : "memory");
}

union f4u { float4 f; ull u[2]; };

// ---------------- Wt prep: g_wt16[outrow][d-permuted] f16 ----------------
// grid 192, 64 thr. outrow = which*64 + h*16 + e.
__global__ __launch_bounds__(64) void wtprep_kernel(
    const float* __restrict__ Wq, const float* __restrict__ Wk, const float* __restrict__ Wv)
{
    int outrow = blockIdx.x;
    int which = outrow >> 6, he = outrow & 63;
    int h = he >> 4, e = he & 15;
    const float* W = (which == 0) ? Wq : (which == 1) ? Wk : Wv;
    int d = threadIdx.x;
    float val = W[(h*DD + d)*HDD + e];
    int dp = (d & 48) + permpos(d & 15);
    g_wt16[outrow*64 + dp] = __float2half(val);
}

// ---------------- proj via MMA: q/k/v from x in one GEMM ----------------
// grid 256, 128 thr. Block covers 64 rows; warp w: rows blockIdx*64 + w*16.
__global__ __launch_bounds__(128) void projmma_kernel(
    const float* __restrict__ x,
    const float* __restrict__ bq, const float* __restrict__ bk, const float* __restrict__ bv,
    float qscale)
{
    __shared__ __align__(16) char swt[192*160];    // Wt16, 160B row stride (conflict-free)
    __shared__ __align__(16) char sxf[8192];       // x A-fragments: 4 warp-tiles x 4 ksteps x 512B
    __shared__ float sbias[192];

    int tid = threadIdx.x, w = tid >> 5, lane = tid & 31;
    int g = lane >> 2, tg = lane & 3;
    int row0 = blockIdx.x * 64;

    uint32_t swtb = smem_u32(swt), sxfb = smem_u32(sxf);

    // stage Wt16: 1536 16B-chunks over 128 threads = 12 each
    #pragma unroll
    for (int i = 0; i < 12; i++) {
        int ci = tid + i*128;
        int r = ci >> 3, c = ci & 7;
        cpa16(swtb + r*160 + c*16, g_wt16 + r*64 + c*8);
    }
    CP_COMMIT();

    // biases
    if (tid < 64)            sbias[tid]       = bq[tid];
    else                     sbias[tid]       = bk[tid - 64];
    if (tid < 64)            sbias[tid + 128] = bv[tid];

    // stage x rows -> f16 permuted A-fragments. thread: row r = tid>>1, k-half kh = tid&1.
    {
        int r = tid >> 1, kh = tid & 1;
        const float4* xr = (const float4*)(x + (size_t)(row0 + r)*DD + kh*32);
        int wt = r >> 4, rr = r & 15;
        uint32_t base = sxfb + wt*2048 + ((rr>>3)&1)*256 + (rr&7)*32;
        #pragma unroll
        for (int gi = 0; gi < 2; gi++) {
            float4 a = xr[gi*4+0], b = xr[gi*4+1], c = xr[gi*4+2], d = xr[gi*4+3];
            int ks = kh*2 + gi;
            sts128(base + ks*512,      pkh2(a.x,a.y), pkh2(c.x,c.y), pkh2(a.z,a.w), pkh2(c.z,c.w));
            sts128(base + ks*512 + 16, pkh2(b.x,b.y), pkh2(d.x,d.y), pkh2(b.z,b.w), pkh2(d.z,d.w));
        }
    }
    CP_WAIT0();
    __syncthreads();

    // load A fragments (16 regs)
    uint32_t A0[4], A1[4], A2[4], A3[4];
    {
        uint32_t base = sxfb + w*2048 + lane*8;
        #pragma unroll
        for (int ks = 0; ks < 4; ks++) {
            uint2 lo = *(const uint2*)(size_t)(0); // placeholder avoided below
            (void)lo;
            uint2 p0, p1;
            asm volatile("ld.shared.v2.b32 {%0,%1}, [%2];" : "=r"(p0.x), "=r"(p0.y) : "r"(base + ks*512));
            asm volatile("ld.shared.v2.b32 {%0,%1}, [%2];" : "=r"(p1.x), "=r"(p1.y) : "r"(base + ks*512 + 256));
            A0[ks] = p0.x; A2[ks] = p0.y; A1[ks] = p1.x; A3[ks] = p1.y;
        }
    }

    int srow = row0 + w*16;
    int bs0 = srow + g;
    int b0i = bs0 >> 12, s0i = bs0 & (SS-1);
    int bs1 = srow + 8 + g;
    int b1i = bs1 >> 12, s1i = bs1 & (SS-1);

    #pragma unroll
    for (int nc = 0; nc < 24; nc++) {
        int which = nc >> 3, hcol = nc & 7;
        int h = hcol >> 1, eh = hcol & 1;
        float d[4] = {0.f, 0.f, 0.f, 0.f};
        uint32_t brow = swtb + (nc*8 + g)*160 + tg*8;
        #pragma unroll
        for (int ks = 0; ks < 4; ks++) {
            uint2 bfr;
            asm volatile("ld.shared.v2.b32 {%0,%1}, [%2];" : "=r"(bfr.x), "=r"(bfr.y) : "r"(brow + ks*32));
            mma16816(d, A0[ks], A1[ks], A2[ks], A3[ks], bfr.x, bfr.y);
        }
        // bias pair for e = eh*8 + 2tg, +1
        float2 bia = *(const float2*)&sbias[which*64 + h*16 + eh*8 + 2*tg];
        if (which == 2) {
            int e = eh*8 + 2*tg;
            *(float2*)&g_v[(size_t)((b0i*HH + h)*SS + s0i)*HDD + e] = make_float2(d[0] + bia.x, d[1] + bia.y);
            *(float2*)&g_v[(size_t)((b1i*HH + h)*SS + s1i)*HDD + e] = make_float2(d[2] + bia.x, d[3] + bia.y);
        } else {
            float sc = (which == 0) ? qscale : 1.0f;
            __half* dst = (which == 0) ? g_q : g_k;
            int slot = 2*tg + eh;   // u32 slot in permuted 16-f16 row
            uint32_t p0 = pkh2((d[0] + bia.x)*sc, (d[1] + bia.y)*sc);
            uint32_t p1 = pkh2((d[2] + bia.x)*sc, (d[3] + bia.y)*sc);
            *(uint32_t*)((char*)(dst + (size_t)((b0i*HH + h)*SS + s0i)*HDD) + slot*4) = p0;
            *(uint32_t*)((char*)(dst + (size_t)((b1i*HH + h)*SS + s1i)*HDD) + slot*4) = p1;
        }
    }
}

// ---------------- Pass A: partial Z_t; 128-thr blocks, warp owns 32 t-rows ----------------
__global__ __launch_bounds__(128, 7) void colsumW_kernel()
{
    __shared__ __align__(16) __half sq[2][2048];
    int tid = threadIdx.x, w = tid >> 5, lane = tid & 31;
    int bh = blockIdx.y, z = blockIdx.z;
    int trow = blockIdx.x * 128 + w * 32;
    const uint32_t ONE2 = 0x3C003C00u;

    const __half* kb = g_k + (size_t)bh*SS*HDD;
    int kg = lane >> 2, ktg = lane & 3;
    uint2 t0a = *((const uint2*)(kb + (trow +      kg)*HDD) + ktg);
    uint2 t0c = *((const uint2*)(kb + (trow +  8 + kg)*HDD) + ktg);
    uint2 t1a = *((const uint2*)(kb + (trow + 16 + kg)*HDD) + ktg);
    uint2 t1c = *((const uint2*)(kb + (trow + 24 + kg)*HDD) + ktg);
    uint32_t a0 = t0a.x, a2 = t0a.y, a1 = t0c.x, a3 = t0c.y;
    uint32_t b0 = t1a.x, b2 = t1a.y, b1 = t1c.x, b3 = t1c.y;

    const __half* qb = g_q + (size_t)bh*SS*HDD + (size_t)z*(SS/2)*HDD;

    int lr0 = tid >> 1, lc0 = tid & 1;
    uint32_t qdst0 = frag_dst(lr0, lc0);
    uint32_t qdst1 = frag_dst(lr0 + 64, lc0);
    const __half* qsrc0 = qb + lr0*HDD + lc0*8;
    const __half* qsrc1 = qb + (lr0 + 64)*HDD + lc0*8;
    uint32_t sqb = smem_u32(sq);

    float zA[4] = {0,0,0,0}, zB[4] = {0,0,0,0};
    float zC[4] = {0,0,0,0}, zD[4] = {0,0,0,0};

    cpa16(sqb + qdst0, qsrc0);
    cpa16(sqb + qdst1, qsrc1);
    CP_COMMIT();

    const int NT = (SS/2)/128;
    for (int tile = 0; tile < NT; tile++) {
        int buf = tile & 1;
        if (tile + 1 < NT) {
            size_t off = (size_t)(tile+1)*128*HDD;
            cpa16(sqb + (buf^1)*4096 + qdst0, qsrc0 + off);
            cpa16(sqb + (buf^1)*4096 + qdst1, qsrc1 + off);
            CP_COMMIT();
            CP_WAIT1();
        } else {
            CP_WAIT0();
        }
        __syncthreads();
        const char* qp = (const char*)sq + buf*4096 + lane*8;
        #pragma unroll
        for (int st = 0; st < 8; st++) {
            uint2 q0 = *(const uint2*)(qp + st*512);
            uint2 q1 = *(const uint2*)(qp + st*512 + 256);
            float d0[4]={0,0,0,0}, d1[4]={0,0,0,0};
            mma16816(d0, a0,a1,a2,a3, q0.x, q0.y);
            mma16816(d1, a0,a1,a2,a3, q1.x, q1.y);
            uint32_t w0 = ex2h2(d0[0], d0[1]);
            uint32_t w1 = ex2h2(d0[2], d0[3]);
            uint32_t w2 = ex2h2(d1[0], d1[1]);
            uint32_t w3 = ex2h2(d1[2], d1[3]);
            mma16816((st & 1) ? zB : zA, w0,w1,w2,w3, ONE2, ONE2);
            float e0[4]={0,0,0,0}, e1[4]={0,0,0,0};
            mma16816(e0, b0,b1,b2,b3, q0.x, q0.y);
            mma16816(e1, b0,b1,b2,b3, q1.x, q1.y);
            uint32_t w4 = ex2h2(e0[0], e0[1]);
            uint32_t w5 = ex2h2(e0[2], e0[3]);
            uint32_t w6 = ex2h2(e1[0], e1[1]);
            uint32_t w7 = ex2h2(e1[2], e1[3]);
            mma16816((st & 1) ? zD : zC, w4,w5,w6,w7, ONE2, ONE2);
        }
        __syncthreads();
    }
    if (ktg == 0) {
        float* zp = g_Zpart + ((size_t)z*BH + bh)*SS + trow;
        zp[kg]      = zA[0] + zB[0];
        zp[8 + kg]  = zA[2] + zB[2];
        zp[16 + kg] = zC[0] + zD[0];
        zp[24 + kg] = zC[2] + zD[2];
    }
}

// ---------------- vnorm ----------------
__global__ __launch_bounds__(256) void vnorm_kernel()
{
    int i = blockIdx.x * 256 + threadIdx.x;
    float r = 1.0f / (g_Zpart[i] + g_Zpart[(size_t)BH*SS + i]);
    int bh = i >> 12, t = i & (SS-1);
    int tp = (t & ~15) + permpos(t & 15);
    const float4* vp = (const float4*)&g_v[(size_t)i*HDD];
    __half* dst = g_vt + (size_t)bh*HDD*SS + tp;
    #pragma unroll
    for (int j = 0; j < 4; j++) {
        float4 v = vp[j];
        dst[(size_t)(4*j+0)*SS] = __float2half(v.x * r);
        dst[(size_t)(4*j+1)*SS] = __float2half(v.y * r);
        dst[(size_t)(4*j+2)*SS] = __float2half(v.z * r);
        dst[(size_t)(4*j+3)*SS] = __float2half(v.w * r);
    }
}

// ---------------- Pass B: partial attended; 128-thr blocks, warp owns 32 s-rows ----------------
__global__ __launch_bounds__(128, 7) void attendW_kernel()
{
    __shared__ __align__(16) __half sk[2][2048];
    __shared__ __align__(16) __half sv[2][2048];
    int tid = threadIdx.x, w = tid >> 5, lane = tid & 31;
    int bh = blockIdx.y, z = blockIdx.z;
    int srow = blockIdx.x * 128 + w * 32;

    const __half* qb = g_q + (size_t)bh*SS*HDD;
    int qg = lane >> 2, qtg = lane & 3;
    uint2 s0a = *((const uint2*)(qb + (srow +      qg)*HDD) + qtg);
    uint2 s0c = *((const uint2*)(qb + (srow +  8 + qg)*HDD) + qtg);
    uint2 s1a = *((const uint2*)(qb + (srow + 16 + qg)*HDD) + qtg);
    uint2 s1c = *((const uint2*)(qb + (srow + 24 + qg)*HDD) + qtg);
    uint32_t a0 = s0a.x, a2 = s0a.y, a1 = s0c.x, a3 = s0c.y;
    uint32_t b0 = s1a.x, b2 = s1a.y, b1 = s1c.x, b3 = s1c.y;

    const __half* kb = g_k + (size_t)bh*SS*HDD + (size_t)z*(SS/2)*HDD;
    const __half* vt = g_vt + (size_t)bh*HDD*SS + (size_t)z*(SS/2);

    int kr0 = tid >> 1, kc0 = tid & 1;
    uint32_t kdst0 = frag_dst(kr0, kc0);
    uint32_t kdst1 = frag_dst(kr0 + 64, kc0);
    const __half* ksrc0 = kb + kr0*HDD + kc0*8;
    const __half* ksrc1 = kb + (kr0 + 64)*HDD + kc0*8;

    int ve0 = tid >> 4, vcv0 = tid & 15;
    int ve1 = (tid + 128) >> 4, vcv1 = tid & 15;
    uint32_t vdst0 = (uint32_t)((vcv0>>1)*512 + (ve0>>3)*256 + (ve0&7)*32 + (vcv0&1)*16);
    uint32_t vdst1 = (uint32_t)((vcv1>>1)*512 + (ve1>>3)*256 + (ve1&7)*32 + (vcv1&1)*16);
    const __half* vsrc0 = vt + (size_t)ve0*SS + vcv0*8;
    const __half* vsrc1 = vt + (size_t)ve1*SS + vcv1*8;

    uint32_t skb = smem_u32(sk), svb = smem_u32(sv);

    float o0[8] = {0,0,0,0,0,0,0,0};
    float o1[8] = {0,0,0,0,0,0,0,0};

    cpa16(skb + kdst0, ksrc0);
    cpa16(skb + kdst1, ksrc1);
    cpa16(svb + vdst0, vsrc0);
    cpa16(svb + vdst1, vsrc1);
    CP_COMMIT();

    const int NT = (SS/2)/128;
    for (int tile = 0; tile < NT; tile++) {
        int buf = tile & 1;
        if (tile + 1 < NT) {
            size_t koff = (size_t)(tile+1)*128*HDD;
            cpa16(skb + (buf^1)*4096 + kdst0, ksrc0 + koff);
            cpa16(skb + (buf^1)*4096 + kdst1, ksrc1 + koff);
            cpa16(svb + (buf^1)*4096 + vdst0, vsrc0 + (size_t)(tile+1)*128);
            cpa16(svb + (buf^1)*4096 + vdst1, vsrc1 + (size_t)(tile+1)*128);
            CP_COMMIT();
            CP_WAIT1();
        } else {
            CP_WAIT0();
        }
        __syncthreads();
        const char* kp = (const char*)sk + buf*4096 + lane*8;
        const char* vp = (const char*)sv + buf*4096 + lane*8;
        #pragma unroll
        for (int st = 0; st < 8; st++) {
            uint2 k0 = *(const uint2*)(kp + st*512);
            uint2 k1 = *(const uint2*)(kp + st*512 + 256);
            uint2 v0 = *(const uint2*)(vp + st*512);
            uint2 v1 = *(const uint2*)(vp + st*512 + 256);
            float d0[4] = {0,0,0,0}, d1[4] = {0,0,0,0};
            mma16816(d0, a0,a1,a2,a3, k0.x, k0.y);
            mma16816(d1, a0,a1,a2,a3, k1.x, k1.y);
            uint32_t w0 = ex2h2(d0[0], d0[1]);
            uint32_t w1 = ex2h2(d0[2], d0[3]);
            uint32_t w2 = ex2h2(d1[0], d1[1]);
            uint32_t w3 = ex2h2(d1[2], d1[3]);
            mma16816(o0,     w0,w1,w2,w3, v0.x, v0.y);
            mma16816(o0 + 4, w0,w1,w2,w3, v1.x, v1.y);
            float e0[4] = {0,0,0,0}, e1[4] = {0,0,0,0};
            mma16816(e0, b0,b1,b2,b3, k0.x, k0.y);
            mma16816(e1, b0,b1,b2,b3, k1.x, k1.y);
            uint32_t w4 = ex2h2(e0[0], e0[1]);
            uint32_t w5 = ex2h2(e0[2], e0[3]);
            uint32_t w6 = ex2h2(e1[0], e1[1]);
            uint32_t w7 = ex2h2(e1[2], e1[3]);
            mma16816(o1,     w4,w5,w6,w7, v0.x, v0.y);
            mma16816(o1 + 4, w4,w5,w6,w7, v1.x, v1.y);
        }
        __syncthreads();
    }

    int b = bh >> 2, h = bh & 3;
    float* att = g_att + (size_t)z*BB*SS*DD + (size_t)h*HDD;
    {
        float* dst0 = att + (size_t)(b*SS + srow + qg)*DD;
        float* dst1 = att + (size_t)(b*SS + srow + 8 + qg)*DD;
        *(float2*)(dst0 + 2*qtg)     = make_float2(o0[0], o0[1]);
        *(float2*)(dst1 + 2*qtg)     = make_float2(o0[2], o0[3]);
        *(float2*)(dst0 + 8 + 2*qtg) = make_float2(o0[4], o0[5]);
        *(float2*)(dst1 + 8 + 2*qtg) = make_float2(o0[6], o0[7]);
    }
    {
        float* dst0 = att + (size_t)(b*SS + srow + 16 + qg)*DD;
        float* dst1 = att + (size_t)(b*SS + srow + 24 + qg)*DD;
        *(float2*)(dst0 + 2*qtg)     = make_float2(o1[0], o1[1]);
        *(float2*)(dst1 + 2*qtg)     = make_float2(o1[2], o1[3]);
        *(float2*)(dst0 + 8 + 2*qtg) = make_float2(o1[4], o1[5]);
        *(float2*)(dst1 + 8 + 2*qtg) = make_float2(o1[6], o1[7]);
    }
}

// ---------------- out_proj ----------------
__global__ __launch_bounds__(256) void out_proj_kernel(
    const float* __restrict__ Wo, const float* __restrict__ bo)
{
    __shared__ float cs[16][64];
    __shared__ float wt[64][68];
    __shared__ float red[4][64];
    int tid = threadIdx.x;
    int row0 = blockIdx.x * 16;
    const float LOG2E = 1.4426950408889634f;

    for (int i = tid; i < 64*64; i += 256) {
        int c = i >> 6, d = i & 63;
        wt[d][c] = Wo[i];
    }
    for (int i = tid; i < 16*64; i += 256)
        cs[i>>6][i&63] = g_att[row0*64 + i] + g_att[(size_t)BB*SS*DD + row0*64 + i];
    __syncthreads();

    int d = tid & 63, r = tid >> 6;
    float bb = bo[d];
    const float4* wrow = (const float4*)&wt[d][0];
    float local = 0.f;

    #pragma unroll
    for (int rr = 0; rr < 4; rr++) {
        int row = r + rr*4;
        const float4* crow = (const float4*)&cs[row][0];
        ull ap = 0ULL, aq = 0ULL;
        #pragma unroll
        for (int j = 0; j < 16; j++) {
            f4u cv, wv;
            cv.f = crow[j]; wv.f = wrow[j];
            ap = ffma2(cv.u[0], wv.u[0], ap);
            aq = ffma2(cv.u[1], wv.u[1], aq);
        }
        float2 p = unpk(ap), q = unpk(aq);
        float acc = (p.x + p.y) + (q.x + q.y);
        float ev = ex2f((acc + bb) * LOG2E);
        g_o[(row0 + row)*64 + d] = ev;
        local += ev;
    }
    red[r][d] = local;
    __syncthreads();
    if (r == 0)
        g_Zop[blockIdx.x*64 + d] = red[0][d] + red[1][d] + red[2][d] + red[3][d];
}

// ---------------- zsum ----------------
__global__ __launch_bounds__(256) void zsum_kernel()
{
    __shared__ float red[4][64];
    int b = blockIdx.x;
    int d = threadIdx.x & 63, cg = threadIdx.x >> 6;
    float s = 0.f;
    for (int c = cg; c < 256; c += 4)
        s += g_Zop[(b*256 + c)*64 + d];
    red[cg][d] = s;
    __syncthreads();
    if (cg == 0)
        g_Zo[b*64 + d] = red[0][d] + red[1][d] + red[2][d] + red[3][d];
}

// ---------------- final ----------------
__global__ __launch_bounds__(256) void final_scale_kernel(float* __restrict__ out)
{
    int idx = blockIdx.x * 256 + threadIdx.x;
    int row = idx >> 4;
    int b = row >> 12;
    int d4 = idx & 15;
    float4 e = ((const float4*)g_o)[idx];
    float4 zz = ((const float4*)g_Zo)[b*16 + d4];
    float4 o;
    o.x = __fdividef(e.x, zz.x);
    o.y = __fdividef(e.y, zz.y);
    o.z = __fdividef(e.z, zz.z);
    o.w = __fdividef(e.w, zz.w);
    ((float4*)out)[idx] = o;
}

// ---------------- launch ----------------
extern "C" void kernel_launch(void* const* d_in, const int* in_sizes, int n_in,
                              void* d_out, int out_size)
{
    const float* x  = (const float*)d_in[0];
    const float* Wq = (const float*)d_in[1];
    const float* bq = (const float*)d_in[2];
    const float* Wk = (const float*)d_in[3];
    const float* bk = (const float*)d_in[4];
    const float* Wv = (const float*)d_in[5];
    const float* bv = (const float*)d_in[6];
    const float* Wo = (const float*)d_in[7];
    const float* bo = (const float*)d_in[8];
    float* out = (float*)d_out;

    const float qscale = 0.25f * 1.4426950408889634f;  // 1/sqrt(HD) * log2(e)

    wtprep_kernel<<<192, 64>>>(Wq, Wk, Wv);
    projmma_kernel<<<256, 128>>>(x, bq, bk, bv, qscale);

    colsumW_kernel<<<dim3(32, BH, 2), 128>>>();
    vnorm_kernel<<<(BH*SS)/256, 256>>>();
    attendW_kernel<<<dim3(32, BH, 2), 128>>>();

    out_proj_kernel<<<BB*SS/16, 256>>>(Wo, bo);
    zsum_kernel<<<BB, 256>>>();
    final_scale_kernel<<<(BB*SS*DD/4)/256, 256>>>(out);
}

// round 13
// speedup vs baseline: 1.3746x; 1.0252x over previous
#include <cuda_runtime.h>
#include <cuda_fp16.h>
#include <cstdint>

#define BB 4
#define SS 4096
#define DD 64
#define HH 4
#define HDD 16
#define BH (BB*HH)

typedef unsigned long long ull;

// q/k: f16, per-row 16 elements stored PERMUTED: pos(e) = 4*((e>>1)&3) + 2*(e>>3) + (e&1)
__device__ __half g_q[BH*SS*HDD];      // 2 MB, scaled by 0.25*log2(e)
__device__ __half g_k[BH*SS*HDD];      // 2 MB
__device__ float  g_v[BH*SS*HDD];      // 4 MB
__device__ __half g_vt[BH*HDD*SS];     // 2 MB, [bh*16+e][t], t permuted per 16-group
__device__ __half g_wt16[192*64];      // 24 KB: [which*64+h*16+e][d permuted], B-frag-ready
__device__ float  g_Zpart[2*BH*SS];    // 512 KB
__device__ float  g_att[2*BB*SS*DD];   // 8 MB attend partials (concat layout)
__device__ float  g_o[BB*SS*DD];       // 4 MB, holds exp(o)
__device__ float  g_Zop[1024*64];      // 256 KB per-block column partials
__device__ float  g_Zo[BB*DD];         // final column sums

// ---------------- helpers ----------------
__device__ __forceinline__ void mma16816(float* d,
    uint32_t a0, uint32_t a1, uint32_t a2, uint32_t a3,
    uint32_t b0, uint32_t b1)
{
    asm volatile("mma.sync.aligned.m16n8k16.row.col.f32.f16.f16.f32 "
        "{%0,%1,%2,%3}, {%4,%5,%6,%7}, {%8,%9}, {%0,%1,%2,%3};"
        : "+f"(d[0]), "+f"(d[1]), "+f"(d[2]), "+f"(d[3])
        : "r"(a0), "r"(a1), "r"(a2), "r"(a3), "r"(b0), "r"(b1));
}
// f16-accumulator variant: D fragment = 2 f16x2 regs, identical packing to an A-fragment
__device__ __forceinline__ void mma16816h(uint32_t* d,
    uint32_t a0, uint32_t a1, uint32_t a2, uint32_t a3,
    uint32_t b0, uint32_t b1)
{
    asm volatile("mma.sync.aligned.m16n8k16.row.col.f16.f16.f16.f16 "
        "{%0,%1}, {%2,%3,%4,%5}, {%6,%7}, {%0,%1};"
        : "+r"(d[0]), "+r"(d[1])
        : "r"(a0), "r"(a1), "r"(a2), "r"(a3), "r"(b0), "r"(b1));
}
__device__ __forceinline__ uint32_t ex2p(uint32_t h)
{
    uint32_t r; asm("ex2.approx.f16x2 %0, %1;" : "=r"(r) : "r"(h)); return r;
}
__device__ __forceinline__ uint32_t pkh2(float lo, float hi)
{
    uint32_t h;
    asm("cvt.rn.f16x2.f32 %0, %1, %2;" : "=r"(h) : "f"(hi), "f"(lo));
    return h;
}
__device__ __forceinline__ float ex2f(float x) {
    float y; asm("ex2.approx.f32 %0, %1;" : "=f"(y) : "f"(x)); return y;
}
__device__ __forceinline__ ull ffma2(ull a, ull b, ull c) {
    ull d; asm("fma.rn.f32x2 %0, %1, %2, %3;" : "=l"(d) : "l"(a), "l"(b), "l"(c)); return d;
}
__device__ __forceinline__ float2 unpk(ull v) {
    float2 f; asm("mov.b64 {%0, %1}, %2;" : "=f"(f.x), "=f"(f.y) : "l"(v)); return f;
}
__device__ __forceinline__ int permpos(int e)
{
    return 4*((e>>1)&3) + 2*(e>>3) + (e&1);
}
__device__ __forceinline__ uint32_t smem_u32(const void* p) {
    uint32_t a; asm("{ .reg .u64 t; cvta.to.shared.u64 t, %1; cvt.u32.u64 %0, t; }" : "=r"(a) : "l"(p));
    return a;
}
__device__ __forceinline__ void cpa16(uint32_t s, const void* g) {
    asm volatile("cp.async.cg.shared.global [%0], [%1], 16;" :: "r"(s), "l"(g));
}
#define CP_COMMIT() asm volatile("cp.async.commit_group;")
#define CP_WAIT1()  asm volatile("cp.async.wait_group 1;")
#define CP_WAIT0()  asm volatile("cp.async.wait_group 0;")

__device__ __forceinline__ uint32_t frag_dst(int r, int c) {
    return (uint32_t)((r>>4)*512 + ((r>>3)&1)*256 + (r&7)*32 + c*16);
}
__device__ __forceinline__ void sts128(uint32_t a, uint32_t x, uint32_t y, uint32_t z, uint32_t w) {
    asm volatile("st.shared.v4.b32 [%0], {%1,%2,%3,%4};" :: "r"(a), "r"(x), "r"(y), "r"(z), "r"(w) : "memory");
}

union f4u { float4 f; ull u[2]; };

// ---------------- Wt prep ----------------
__global__ __launch_bounds__(64) void wtprep_kernel(
    const float* __restrict__ Wq, const float* __restrict__ Wk, const float* __restrict__ Wv)
{
    int outrow = blockIdx.x;
    int which = outrow >> 6, he = outrow & 63;
    int h = he >> 4, e = he & 15;
    const float* W = (which == 0) ? Wq : (which == 1) ? Wk : Wv;
    int d = threadIdx.x;
    float val = W[(h*DD + d)*HDD + e];
    int dp = (d & 48) + permpos(d & 15);
    g_wt16[outrow*64 + dp] = __float2half(val);
}

// ---------------- proj via MMA ----------------
__global__ __launch_bounds__(128) void projmma_kernel(
    const float* __restrict__ x,
    const float* __restrict__ bq, const float* __restrict__ bk, const float* __restrict__ bv,
    float qscale)
{
    __shared__ __align__(16) char swt[192*160];
    __shared__ __align__(16) char sxf[8192];
    __shared__ float sbias[192];

    int tid = threadIdx.x, w = tid >> 5, lane = tid & 31;
    int g = lane >> 2, tg = lane & 3;
    int row0 = blockIdx.x * 64;

    uint32_t swtb = smem_u32(swt), sxfb = smem_u32(sxf);

    #pragma unroll
    for (int i = 0; i < 12; i++) {
        int ci = tid + i*128;
        int r = ci >> 3, c = ci & 7;
        cpa16(swtb + r*160 + c*16, g_wt16 + r*64 + c*8);
    }
    CP_COMMIT();

    if (tid < 64)            sbias[tid]       = bq[tid];
    else                     sbias[tid]       = bk[tid - 64];
    if (tid < 64)            sbias[tid + 128] = bv[tid];

    {
        int r = tid >> 1, kh = tid & 1;
        const float4* xr = (const float4*)(x + (size_t)(row0 + r)*DD + kh*32);
        int wt = r >> 4, rr = r & 15;
        uint32_t base = sxfb + wt*2048 + ((rr>>3)&1)*256 + (rr&7)*32;
        #pragma unroll
        for (int gi = 0; gi < 2; gi++) {
            float4 a = xr[gi*4+0], b = xr[gi*4+1], c = xr[gi*4+2], d = xr[gi*4+3];
            int ks = kh*2 + gi;
            sts128(base + ks*512,      pkh2(a.x,a.y), pkh2(c.x,c.y), pkh2(a.z,a.w), pkh2(c.z,c.w));
            sts128(base + ks*512 + 16, pkh2(b.x,b.y), pkh2(d.x,d.y), pkh2(b.z,b.w), pkh2(d.z,d.w));
        }
    }
    CP_WAIT0();
    __syncthreads();

    uint32_t A0[4], A1[4], A2[4], A3[4];
    {
        uint32_t base = sxfb + w*2048 + lane*8;
        #pragma unroll
        for (int ks = 0; ks < 4; ks++) {
            uint2 p0, p1;
            asm volatile("ld.shared.v2.b32 {%0,%1}, [%2];" : "=r"(p0.x), "=r"(p0.y) : "r"(base + ks*512));
            asm volatile("ld.shared.v2.b32 {%0,%1}, [%2];" : "=r"(p1.x), "=r"(p1.y) : "r"(base + ks*512 + 256));
            A0[ks] = p0.x; A2[ks] = p0.y; A1[ks] = p1.x; A3[ks] = p1.y;
        }
    }

    int srow = row0 + w*16;
    int bs0 = srow + g;
    int b0i = bs0 >> 12, s0i = bs0 & (SS-1);
    int bs1 = srow + 8 + g;
    int b1i = bs1 >> 12, s1i = bs1 & (SS-1);

    #pragma unroll
    for (int nc = 0; nc < 24; nc++) {
        int which = nc >> 3, hcol = nc & 7;
        int h = hcol >> 1, eh = hcol & 1;
        float d[4] = {0.f, 0.f, 0.f, 0.f};
        uint32_t brow = swtb + (nc*8 + g)*160 + tg*8;
        #pragma unroll
        for (int ks = 0; ks < 4; ks++) {
            uint2 bfr;
            asm volatile("ld.shared.v2.b32 {%0,%1}, [%2];" : "=r"(bfr.x), "=r"(bfr.y) : "r"(brow + ks*32));
            mma16816(d, A0[ks], A1[ks], A2[ks], A3[ks], bfr.x, bfr.y);
        }
        float2 bia = *(const float2*)&sbias[which*64 + h*16 + eh*8 + 2*tg];
        if (which == 2) {
            int e = eh*8 + 2*tg;
            *(float2*)&g_v[(size_t)((b0i*HH + h)*SS + s0i)*HDD + e] = make_float2(d[0] + bia.x, d[1] + bia.y);
            *(float2*)&g_v[(size_t)((b1i*HH + h)*SS + s1i)*HDD + e] = make_float2(d[2] + bia.x, d[3] + bia.y);
        } else {
            float sc = (which == 0) ? qscale : 1.0f;
            __half* dst = (which == 0) ? g_q : g_k;
            int slot = 2*tg + eh;
            uint32_t p0 = pkh2((d[0] + bia.x)*sc, (d[1] + bia.y)*sc);
            uint32_t p1 = pkh2((d[2] + bia.x)*sc, (d[3] + bia.y)*sc);
            *(uint32_t*)((char*)(dst + (size_t)((b0i*HH + h)*SS + s0i)*HDD) + slot*4) = p0;
            *(uint32_t*)((char*)(dst + (size_t)((b1i*HH + h)*SS + s1i)*HDD) + slot*4) = p1;
        }
    }
}

// ---------------- Pass A: partial Z_t; f16-D score MMAs ----------------
__global__ __launch_bounds__(128, 7) void colsumW_kernel()
{
    __shared__ __align__(16) __half sq[2][2048];
    int tid = threadIdx.x, w = tid >> 5, lane = tid & 31;
    int bh = blockIdx.y, z = blockIdx.z;
    int trow = blockIdx.x * 128 + w * 32;
    const uint32_t ONE2 = 0x3C003C00u;

    const __half* kb = g_k + (size_t)bh*SS*HDD;
    int kg = lane >> 2, ktg = lane & 3;
    uint2 t0a = *((const uint2*)(kb + (trow +      kg)*HDD) + ktg);
    uint2 t0c = *((const uint2*)(kb + (trow +  8 + kg)*HDD) + ktg);
    uint2 t1a = *((const uint2*)(kb + (trow + 16 + kg)*HDD) + ktg);
    uint2 t1c = *((const uint2*)(kb + (trow + 24 + kg)*HDD) + ktg);
    uint32_t a0 = t0a.x, a2 = t0a.y, a1 = t0c.x, a3 = t0c.y;
    uint32_t b0 = t1a.x, b2 = t1a.y, b1 = t1c.x, b3 = t1c.y;

    const __half* qb = g_q + (size_t)bh*SS*HDD + (size_t)z*(SS/2)*HDD;

    int lr0 = tid >> 1, lc0 = tid & 1;
    uint32_t qdst0 = frag_dst(lr0, lc0);
    uint32_t qdst1 = frag_dst(lr0 + 64, lc0);
    const __half* qsrc0 = qb + lr0*HDD + lc0*8;
    const __half* qsrc1 = qb + (lr0 + 64)*HDD + lc0*8;
    uint32_t sqb = smem_u32(sq);

    float zA[4] = {0,0,0,0}, zB[4] = {0,0,0,0};
    float zC[4] = {0,0,0,0}, zD[4] = {0,0,0,0};

    cpa16(sqb + qdst0, qsrc0);
    cpa16(sqb + qdst1, qsrc1);
    CP_COMMIT();

    const int NT = (SS/2)/128;
    for (int tile = 0; tile < NT; tile++) {
        int buf = tile & 1;
        if (tile + 1 < NT) {
            size_t off = (size_t)(tile+1)*128*HDD;
            cpa16(sqb + (buf^1)*4096 + qdst0, qsrc0 + off);
            cpa16(sqb + (buf^1)*4096 + qdst1, qsrc1 + off);
            CP_COMMIT();
            CP_WAIT1();
        } else {
            CP_WAIT0();
        }
        __syncthreads();
        const char* qp = (const char*)sq + buf*4096 + lane*8;
        #pragma unroll
        for (int st = 0; st < 8; st++) {
            uint2 q0 = *(const uint2*)(qp + st*512);
            uint2 q1 = *(const uint2*)(qp + st*512 + 256);
            uint32_t d0[2] = {0,0}, d1[2] = {0,0};
            mma16816h(d0, a0,a1,a2,a3, q0.x, q0.y);
            mma16816h(d1, a0,a1,a2,a3, q1.x, q1.y);
            uint32_t w0 = ex2p(d0[0]);
            uint32_t w1 = ex2p(d0[1]);
            uint32_t w2 = ex2p(d1[0]);
            uint32_t w3 = ex2p(d1[1]);
            mma16816((st & 1) ? zB : zA, w0,w1,w2,w3, ONE2, ONE2);
            uint32_t e0[2] = {0,0}, e1[2] = {0,0};
            mma16816h(e0, b0,b1,b2,b3, q0.x, q0.y);
            mma16816h(e1, b0,b1,b2,b3, q1.x, q1.y);
            uint32_t w4 = ex2p(e0[0]);
            uint32_t w5 = ex2p(e0[1]);
            uint32_t w6 = ex2p(e1[0]);
            uint32_t w7 = ex2p(e1[1]);
            mma16816((st & 1) ? zD : zC, w4,w5,w6,w7, ONE2, ONE2);
        }
        __syncthreads();
    }
    if (ktg == 0) {
        float* zp = g_Zpart + ((size_t)z*BH + bh)*SS + trow;
        zp[kg]      = zA[0] + zB[0];
        zp[8 + kg]  = zA[2] + zB[2];
        zp[16 + kg] = zC[0] + zD[0];
        zp[24 + kg] = zC[2] + zD[2];
    }
}

// ---------------- vnorm ----------------
__global__ __launch_bounds__(256) void vnorm_kernel()
{
    int i = blockIdx.x * 256 + threadIdx.x;
    float r = 1.0f / (g_Zpart[i] + g_Zpart[(size_t)BH*SS + i]);
    int bh = i >> 12, t = i & (SS-1);
    int tp = (t & ~15) + permpos(t & 15);
    const float4* vp = (const float4*)&g_v[(size_t)i*HDD];
    __half* dst = g_vt + (size_t)bh*HDD*SS + tp;
    #pragma unroll
    for (int j = 0; j < 4; j++) {
        float4 v = vp[j];
        dst[(size_t)(4*j+0)*SS] = __float2half(v.x * r);
        dst[(size_t)(4*j+1)*SS] = __float2half(v.y * r);
        dst[(size_t)(4*j+2)*SS] = __float2half(v.z * r);
        dst[(size_t)(4*j+3)*SS] = __float2half(v.w * r);
    }
}

// ---------------- Pass B: partial attended; f16-D score MMAs ----------------
__global__ __launch_bounds__(128, 7) void attendW_kernel()
{
    __shared__ __align__(16) __half sk[2][2048];
    __shared__ __align__(16) __half sv[2][2048];
    int tid = threadIdx.x, w = tid >> 5, lane = tid & 31;
    int bh = blockIdx.y, z = blockIdx.z;
    int srow = blockIdx.x * 128 + w * 32;

    const __half* qb = g_q + (size_t)bh*SS*HDD;
    int qg = lane >> 2, qtg = lane & 3;
    uint2 s0a = *((const uint2*)(qb + (srow +      qg)*HDD) + qtg);
    uint2 s0c = *((const uint2*)(qb + (srow +  8 + qg)*HDD) + qtg);
    uint2 s1a = *((const uint2*)(qb + (srow + 16 + qg)*HDD) + qtg);
    uint2 s1c = *((const uint2*)(qb + (srow + 24 + qg)*HDD) + qtg);
    uint32_t a0 = s0a.x, a2 = s0a.y, a1 = s0c.x, a3 = s0c.y;
    uint32_t b0 = s1a.x, b2 = s1a.y, b1 = s1c.x, b3 = s1c.y;

    const __half* kb = g_k + (size_t)bh*SS*HDD + (size_t)z*(SS/2)*HDD;
    const __half* vt = g_vt + (size_t)bh*HDD*SS + (size_t)z*(SS/2);

    int kr0 = tid >> 1, kc0 = tid & 1;
    uint32_t kdst0 = frag_dst(kr0, kc0);
    uint32_t kdst1 = frag_dst(kr0 + 64, kc0);
    const __half* ksrc0 = kb + kr0*HDD + kc0*8;
    const __half* ksrc1 = kb + (kr0 + 64)*HDD + kc0*8;

    int ve0 = tid >> 4, vcv0 = tid & 15;
    int ve1 = (tid + 128) >> 4, vcv1 = tid & 15;
    uint32_t vdst0 = (uint32_t)((vcv0>>1)*512 + (ve0>>3)*256 + (ve0&7)*32 + (vcv0&1)*16);
    uint32_t vdst1 = (uint32_t)((vcv1>>1)*512 + (ve1>>3)*256 + (ve1&7)*32 + (vcv1&1)*16);
    const __half* vsrc0 = vt + (size_t)ve0*SS + vcv0*8;
    const __half* vsrc1 = vt + (size_t)ve1*SS + vcv1*8;

    uint32_t skb = smem_u32(sk), svb = smem_u32(sv);

    float o0[8] = {0,0,0,0,0,0,0,0};
    float o1[8] = {0,0,0,0,0,0,0,0};

    cpa16(skb + kdst0, ksrc0);
    cpa16(skb + kdst1, ksrc1);
    cpa16(svb + vdst0, vsrc0);
    cpa16(svb + vdst1, vsrc1);
    CP_COMMIT();

    const int NT = (SS/2)/128;
    for (int tile = 0; tile < NT; tile++) {
        int buf = tile & 1;
        if (tile + 1 < NT) {
            size_t koff = (size_t)(tile+1)*128*HDD;
            cpa16(skb + (buf^1)*4096 + kdst0, ksrc0 + koff);
            cpa16(skb + (buf^1)*4096 + kdst1, ksrc1 + koff);
            cpa16(svb + (buf^1)*4096 + vdst0, vsrc0 + (size_t)(tile+1)*128);
            cpa16(svb + (buf^1)*4096 + vdst1, vsrc1 + (size_t)(tile+1)*128);
            CP_COMMIT();
            CP_WAIT1();
        } else {
            CP_WAIT0();
        }
        __syncthreads();
        const char* kp = (const char*)sk + buf*4096 + lane*8;
        const char* vp = (const char*)sv + buf*4096 + lane*8;
        #pragma unroll
        for (int st = 0; st < 8; st++) {
            uint2 k0 = *(const uint2*)(kp + st*512);
            uint2 k1 = *(const uint2*)(kp + st*512 + 256);
            uint2 v0 = *(const uint2*)(vp + st*512);
            uint2 v1 = *(const uint2*)(vp + st*512 + 256);
            uint32_t d0[2] = {0,0}, d1[2] = {0,0};
            mma16816h(d0, a0,a1,a2,a3, k0.x, k0.y);
            mma16816h(d1, a0,a1,a2,a3, k1.x, k1.y);
            uint32_t w0 = ex2p(d0[0]);
            uint32_t w1 = ex2p(d0[1]);
            uint32_t w2 = ex2p(d1[0]);
            uint32_t w3 = ex2p(d1[1]);
            mma16816(o0,     w0,w1,w2,w3, v0.x, v0.y);
            mma16816(o0 + 4, w0,w1,w2,w3, v1.x, v1.y);
            uint32_t e0[2] = {0,0}, e1[2] = {0,0};
            mma16816h(e0, b0,b1,b2,b3, k0.x, k0.y);
            mma16816h(e1, b0,b1,b2,b3, k1.x, k1.y);
            uint32_t w4 = ex2p(e0[0]);
            uint32_t w5 = ex2p(e0[1]);
            uint32_t w6 = ex2p(e1[0]);
            uint32_t w7 = ex2p(e1[1]);
            mma16816(o1,     w4,w5,w6,w7, v0.x, v0.y);
            mma16816(o1 + 4, w4,w5,w6,w7, v1.x, v1.y);
        }
        __syncthreads();
    }

    int b = bh >> 2, h = bh & 3;
    float* att = g_att + (size_t)z*BB*SS*DD + (size_t)h*HDD;
    {
        float* dst0 = att + (size_t)(b*SS + srow + qg)*DD;
        float* dst1 = att + (size_t)(b*SS + srow + 8 + qg)*DD;
        *(float2*)(dst0 + 2*qtg)     = make_float2(o0[0], o0[1]);
        *(float2*)(dst1 + 2*qtg)     = make_float2(o0[2], o0[3]);
        *(float2*)(dst0 + 8 + 2*qtg) = make_float2(o0[4], o0[5]);
        *(float2*)(dst1 + 8 + 2*qtg) = make_float2(o0[6], o0[7]);
    }
    {
        float* dst0 = att + (size_t)(b*SS + srow + 16 + qg)*DD;
        float* dst1 = att + (size_t)(b*SS + srow + 24 + qg)*DD;
        *(float2*)(dst0 + 2*qtg)     = make_float2(o1[0], o1[1]);
        *(float2*)(dst1 + 2*qtg)     = make_float2(o1[2], o1[3]);
        *(float2*)(dst0 + 8 + 2*qtg) = make_float2(o1[4], o1[5]);
        *(float2*)(dst1 + 8 + 2*qtg) = make_float2(o1[6], o1[7]);
    }
}

// ---------------- out_proj ----------------
__global__ __launch_bounds__(256) void out_proj_kernel(
    const float* __restrict__ Wo, const float* __restrict__ bo)
{
    __shared__ float cs[16][64];
    __shared__ float wt[64][68];
    __shared__ float red[4][64];
    int tid = threadIdx.x;
    int row0 = blockIdx.x * 16;
    const float LOG2E = 1.4426950408889634f;

    for (int i = tid; i < 64*64; i += 256) {
        int c = i >> 6, d = i & 63;
        wt[d][c] = Wo[i];
    }
    for (int i = tid; i < 16*64; i += 256)
        cs[i>>6][i&63] = g_att[row0*64 + i] + g_att[(size_t)BB*SS*DD + row0*64 + i];
    __syncthreads();

    int d = tid & 63, r = tid >> 6;
    float bb = bo[d];
    const float4* wrow = (const float4*)&wt[d][0];
    float local = 0.f;

    #pragma unroll
    for (int rr = 0; rr < 4; rr++) {
        int row = r + rr*4;
        const float4* crow = (const float4*)&cs[row][0];
        ull ap = 0ULL, aq = 0ULL;
        #pragma unroll
        for (int j = 0; j < 16; j++) {
            f4u cv, wv;
            cv.f = crow[j]; wv.f = wrow[j];
            ap = ffma2(cv.u[0], wv.u[0], ap);
            aq = ffma2(cv.u[1], wv.u[1], aq);
        }
        float2 p = unpk(ap), q = unpk(aq);
        float acc = (p.x + p.y) + (q.x + q.y);
        float ev = ex2f((acc + bb) * LOG2E);
        g_o[(row0 + row)*64 + d] = ev;
        local += ev;
    }
    red[r][d] = local;
    __syncthreads();
    if (r == 0)
        g_Zop[blockIdx.x*64 + d] = red[0][d] + red[1][d] + red[2][d] + red[3][d];
}

// ---------------- zsum ----------------
__global__ __launch_bounds__(256) void zsum_kernel()
{
    __shared__ float red[4][64];
    int b = blockIdx.x;
    int d = threadIdx.x & 63, cg = threadIdx.x >> 6;
    float s = 0.f;
    for (int c = cg; c < 256; c += 4)
        s += g_Zop[(b*256 + c)*64 + d];
    red[cg][d] = s;
    __syncthreads();
    if (cg == 0)
        g_Zo[b*64 + d] = red[0][d] + red[1][d] + red[2][d] + red[3][d];
}

// ---------------- final ----------------
__global__ __launch_bounds__(256) void final_scale_kernel(float* __restrict__ out)
{
    int idx = blockIdx.x * 256 + threadIdx.x;
    int row = idx >> 4;
    int b = row >> 12;
    int d4 = idx & 15;
    float4 e = ((const float4*)g_o)[idx];
    float4 zz = ((const float4*)g_Zo)[b*16 + d4];
    float4 o;
    o.x = __fdividef(e.x, zz.x);
    o.y = __fdividef(e.y, zz.y);
    o.z = __fdividef(e.z, zz.z);
    o.w = __fdividef(e.w, zz.w);
    ((float4*)out)[idx] = o;
}

// ---------------- launch ----------------
extern "C" void kernel_launch(void* const* d_in, const int* in_sizes, int n_in,
                              void* d_out, int out_size)
{
    const float* x  = (const float*)d_in[0];
    const float* Wq = (const float*)d_in[1];
    const float* bq = (const float*)d_in[2];
    const float* Wk = (const float*)d_in[3];
    const float* bk = (const float*)d_in[4];
    const float* Wv = (const float*)d_in[5];
    const float* bv = (const float*)d_in[6];
    const float* Wo = (const float*)d_in[7];
    const float* bo = (const float*)d_in[8];
    float* out = (float*)d_out;

    const float qscale = 0.25f * 1.4426950408889634f;  // 1/sqrt(HD) * log2(e)

    wtprep_kernel<<<192, 64>>>(Wq, Wk, Wv);
    projmma_kernel<<<256, 128>>>(x, bq, bk, bv, qscale);

    colsumW_kernel<<<dim3(32, BH, 2), 128>>>();
    vnorm_kernel<<<(BH*SS)/256, 256>>>();
    attendW_kernel<<<dim3(32, BH, 2), 128>>>();

    out_proj_kernel<<<BB*SS/16, 256>>>(Wo, bo);
    zsum_kernel<<<BB, 256>>>();
    final_scale_kernel<<<(BB*SS*DD/4)/256, 256>>>(out);
}

// round 14
// speedup vs baseline: 1.4781x; 1.0753x over previous
#include <cuda_runtime.h>
#include <cuda_fp16.h>
#include <cstdint>

#define BB 4
#define SS 4096
#define DD 64
#define HH 4
#define HDD 16
#define BH (BB*HH)

typedef unsigned long long ull;

// q/k: f16, per-row 16 elements stored PERMUTED: pos(e) = 4*((e>>1)&3) + 2*(e>>3) + (e&1)
__device__ __half g_q[BH*SS*HDD];      // 2 MB, scaled by 0.25*log2(e)
__device__ __half g_k[BH*SS*HDD];      // 2 MB
__device__ float  g_v[BH*SS*HDD];      // 4 MB
__device__ __half g_vt[BH*HDD*SS];     // 2 MB, [bh*16+e][t], t permuted per 16-group
__device__ __half g_wt16[192*64];      // 24 KB: [which*64+h*16+e][d permuted], B-frag-ready
__device__ float  g_Zpart[2*BH*SS];    // 512 KB
__device__ float  g_att[2*BB*SS*DD];   // 8 MB attend partials (concat layout)
__device__ float  g_o[BB*SS*DD];       // 4 MB, holds exp(o)
__device__ float  g_Zop[1024*64];      // per-block column partials
__device__ float  g_Zo[BB*DD];         // final column sums

// ---------------- helpers ----------------
__device__ __forceinline__ void mma16816(float* d,
    uint32_t a0, uint32_t a1, uint32_t a2, uint32_t a3,
    uint32_t b0, uint32_t b1)
{
    asm volatile("mma.sync.aligned.m16n8k16.row.col.f32.f16.f16.f32 "
        "{%0,%1,%2,%3}, {%4,%5,%6,%7}, {%8,%9}, {%0,%1,%2,%3};"
        : "+f"(d[0]), "+f"(d[1]), "+f"(d[2]), "+f"(d[3])
        : "r"(a0), "r"(a1), "r"(a2), "r"(a3), "r"(b0), "r"(b1));
}
__device__ __forceinline__ void mma16816h(uint32_t* d,
    uint32_t a0, uint32_t a1, uint32_t a2, uint32_t a3,
    uint32_t b0, uint32_t b1)
{
    asm volatile("mma.sync.aligned.m16n8k16.row.col.f16.f16.f16.f16 "
        "{%0,%1}, {%2,%3,%4,%5}, {%6,%7}, {%0,%1};"
        : "+r"(d[0]), "+r"(d[1])
        : "r"(a0), "r"(a1), "r"(a2), "r"(a3), "r"(b0), "r"(b1));
}
__device__ __forceinline__ uint32_t ex2p(uint32_t h)
{
    uint32_t r; asm("ex2.approx.f16x2 %0, %1;" : "=r"(r) : "r"(h)); return r;
}
__device__ __forceinline__ uint32_t pkh2(float lo, float hi)
{
    uint32_t h;
    asm("cvt.rn.f16x2.f32 %0, %1, %2;" : "=r"(h) : "f"(hi), "f"(lo));
    return h;
}
__device__ __forceinline__ float ex2f(float x) {
    float y; asm("ex2.approx.f32 %0, %1;" : "=f"(y) : "f"(x)); return y;
}
__device__ __forceinline__ int permpos(int e)
{
    return 4*((e>>1)&3) + 2*(e>>3) + (e&1);
}
__device__ __forceinline__ uint32_t smem_u32(const void* p) {
    uint32_t a; asm("{ .reg .u64 t; cvta.to.shared.u64 t, %1; cvt.u32.u64 %0, t; }" : "=r"(a) : "l"(p));
    return a;
}
__device__ __forceinline__ void cpa16(uint32_t s, const void* g) {
    asm volatile("cp.async.cg.shared.global [%0], [%1], 16;" :: "r"(s), "l"(g));
}
#define CP_COMMIT() asm volatile("cp.async.commit_group;")
#define CP_WAIT1()  asm volatile("cp.async.wait_group 1;")
#define CP_WAIT0()  asm volatile("cp.async.wait_group 0;")

__device__ __forceinline__ uint32_t frag_dst(int r, int c) {
    return (uint32_t)((r>>4)*512 + ((r>>3)&1)*256 + (r&7)*32 + c*16);
}
__device__ __forceinline__ void sts128(uint32_t a, uint32_t x, uint32_t y, uint32_t z, uint32_t w) {
    asm volatile("st.shared.v4.b32 [%0], {%1,%2,%3,%4};" :: "r"(a), "r"(x), "r"(y), "r"(z), "r"(w) : "memory");
}

// ---------------- Wt prep ----------------
__global__ __launch_bounds__(64) void wtprep_kernel(
    const float* __restrict__ Wq, const float* __restrict__ Wk, const float* __restrict__ Wv)
{
    int outrow = blockIdx.x;
    int which = outrow >> 6, he = outrow & 63;
    int h = he >> 4, e = he & 15;
    const float* W = (which == 0) ? Wq : (which == 1) ? Wk : Wv;
    int d = threadIdx.x;
    float val = W[(h*DD + d)*HDD + e];
    int dp = (d & 48) + permpos(d & 15);
    g_wt16[outrow*64 + dp] = __float2half(val);
}

// ---------------- proj via MMA ----------------
__global__ __launch_bounds__(128) void projmma_kernel(
    const float* __restrict__ x,
    const float* __restrict__ bq, const float* __restrict__ bk, const float* __restrict__ bv,
    float qscale)
{
    __shared__ __align__(16) char swt[192*160];
    __shared__ __align__(16) char sxf[8192];
    __shared__ float sbias[192];

    int tid = threadIdx.x, w = tid >> 5, lane = tid & 31;
    int g = lane >> 2, tg = lane & 3;
    int row0 = blockIdx.x * 64;

    uint32_t swtb = smem_u32(swt), sxfb = smem_u32(sxf);

    #pragma unroll
    for (int i = 0; i < 12; i++) {
        int ci = tid + i*128;
        int r = ci >> 3, c = ci & 7;
        cpa16(swtb + r*160 + c*16, g_wt16 + r*64 + c*8);
    }
    CP_COMMIT();

    if (tid < 64)            sbias[tid]       = bq[tid];
    else                     sbias[tid]       = bk[tid - 64];
    if (tid < 64)            sbias[tid + 128] = bv[tid];

    {
        int r = tid >> 1, kh = tid & 1;
        const float4* xr = (const float4*)(x + (size_t)(row0 + r)*DD + kh*32);
        int wt = r >> 4, rr = r & 15;
        uint32_t base = sxfb + wt*2048 + ((rr>>3)&1)*256 + (rr&7)*32;
        #pragma unroll
        for (int gi = 0; gi < 2; gi++) {
            float4 a = xr[gi*4+0], b = xr[gi*4+1], c = xr[gi*4+2], d = xr[gi*4+3];
            int ks = kh*2 + gi;
            sts128(base + ks*512,      pkh2(a.x,a.y), pkh2(c.x,c.y), pkh2(a.z,a.w), pkh2(c.z,c.w));
            sts128(base + ks*512 + 16, pkh2(b.x,b.y), pkh2(d.x,d.y), pkh2(b.z,b.w), pkh2(d.z,d.w));
        }
    }
    CP_WAIT0();
    __syncthreads();

    uint32_t A0[4], A1[4], A2[4], A3[4];
    {
        uint32_t base = sxfb + w*2048 + lane*8;
        #pragma unroll
        for (int ks = 0; ks < 4; ks++) {
            uint2 p0, p1;
            asm volatile("ld.shared.v2.b32 {%0,%1}, [%2];" : "=r"(p0.x), "=r"(p0.y) : "r"(base + ks*512));
            asm volatile("ld.shared.v2.b32 {%0,%1}, [%2];" : "=r"(p1.x), "=r"(p1.y) : "r"(base + ks*512 + 256));
            A0[ks] = p0.x; A2[ks] = p0.y; A1[ks] = p1.x; A3[ks] = p1.y;
        }
    }

    int srow = row0 + w*16;
    int bs0 = srow + g;
    int b0i = bs0 >> 12, s0i = bs0 & (SS-1);
    int bs1 = srow + 8 + g;
    int b1i = bs1 >> 12, s1i = bs1 & (SS-1);

    #pragma unroll
    for (int nc = 0; nc < 24; nc++) {
        int which = nc >> 3, hcol = nc & 7;
        int h = hcol >> 1, eh = hcol & 1;
        float d[4] = {0.f, 0.f, 0.f, 0.f};
        uint32_t brow = swtb + (nc*8 + g)*160 + tg*8;
        #pragma unroll
        for (int ks = 0; ks < 4; ks++) {
            uint2 bfr;
            asm volatile("ld.shared.v2.b32 {%0,%1}, [%2];" : "=r"(bfr.x), "=r"(bfr.y) : "r"(brow + ks*32));
            mma16816(d, A0[ks], A1[ks], A2[ks], A3[ks], bfr.x, bfr.y);
        }
        float2 bia = *(const float2*)&sbias[which*64 + h*16 + eh*8 + 2*tg];
        if (which == 2) {
            int e = eh*8 + 2*tg;
            *(float2*)&g_v[(size_t)((b0i*HH + h)*SS + s0i)*HDD + e] = make_float2(d[0] + bia.x, d[1] + bia.y);
            *(float2*)&g_v[(size_t)((b1i*HH + h)*SS + s1i)*HDD + e] = make_float2(d[2] + bia.x, d[3] + bia.y);
        } else {
            float sc = (which == 0) ? qscale : 1.0f;
            __half* dst = (which == 0) ? g_q : g_k;
            int slot = 2*tg + eh;
            uint32_t p0 = pkh2((d[0] + bia.x)*sc, (d[1] + bia.y)*sc);
            uint32_t p1 = pkh2((d[2] + bia.x)*sc, (d[3] + bia.y)*sc);
            *(uint32_t*)((char*)(dst + (size_t)((b0i*HH + h)*SS + s0i)*HDD) + slot*4) = p0;
            *(uint32_t*)((char*)(dst + (size_t)((b1i*HH + h)*SS + s1i)*HDD) + slot*4) = p1;
        }
    }
}

// ---------------- Pass A: partial Z_t; f16-D score MMAs ----------------
__global__ __launch_bounds__(128, 7) void colsumW_kernel()
{
    __shared__ __align__(16) __half sq[2][2048];
    int tid = threadIdx.x, w = tid >> 5, lane = tid & 31;
    int bh = blockIdx.y, z = blockIdx.z;
    int trow = blockIdx.x * 128 + w * 32;
    const uint32_t ONE2 = 0x3C003C00u;

    const __half* kb = g_k + (size_t)bh*SS*HDD;
    int kg = lane >> 2, ktg = lane & 3;
    uint2 t0a = *((const uint2*)(kb + (trow +      kg)*HDD) + ktg);
    uint2 t0c = *((const uint2*)(kb + (trow +  8 + kg)*HDD) + ktg);
    uint2 t1a = *((const uint2*)(kb + (trow + 16 + kg)*HDD) + ktg);
    uint2 t1c = *((const uint2*)(kb + (trow + 24 + kg)*HDD) + ktg);
    uint32_t a0 = t0a.x, a2 = t0a.y, a1 = t0c.x, a3 = t0c.y;
    uint32_t b0 = t1a.x, b2 = t1a.y, b1 = t1c.x, b3 = t1c.y;

    const __half* qb = g_q + (size_t)bh*SS*HDD + (size_t)z*(SS/2)*HDD;

    int lr0 = tid >> 1, lc0 = tid & 1;
    uint32_t qdst0 = frag_dst(lr0, lc0);
    uint32_t qdst1 = frag_dst(lr0 + 64, lc0);
    const __half* qsrc0 = qb + lr0*HDD + lc0*8;
    const __half* qsrc1 = qb + (lr0 + 64)*HDD + lc0*8;
    uint32_t sqb = smem_u32(sq);

    float zA[4] = {0,0,0,0}, zB[4] = {0,0,0,0};
    float zC[4] = {0,0,0,0}, zD[4] = {0,0,0,0};

    cpa16(sqb + qdst0, qsrc0);
    cpa16(sqb + qdst1, qsrc1);
    CP_COMMIT();

    const int NT = (SS/2)/128;
    for (int tile = 0; tile < NT; tile++) {
        int buf = tile & 1;
        if (tile + 1 < NT) {
            size_t off = (size_t)(tile+1)*128*HDD;
            cpa16(sqb + (buf^1)*4096 + qdst0, qsrc0 + off);
            cpa16(sqb + (buf^1)*4096 + qdst1, qsrc1 + off);
            CP_COMMIT();
            CP_WAIT1();
        } else {
            CP_WAIT0();
        }
        __syncthreads();
        const char* qp = (const char*)sq + buf*4096 + lane*8;
        #pragma unroll
        for (int st = 0; st < 8; st++) {
            uint2 q0 = *(const uint2*)(qp + st*512);
            uint2 q1 = *(const uint2*)(qp + st*512 + 256);
            uint32_t d0[2] = {0,0}, d1[2] = {0,0};
            mma16816h(d0, a0,a1,a2,a3, q0.x, q0.y);
            mma16816h(d1, a0,a1,a2,a3, q1.x, q1.y);
            uint32_t w0 = ex2p(d0[0]);
            uint32_t w1 = ex2p(d0[1]);
            uint32_t w2 = ex2p(d1[0]);
            uint32_t w3 = ex2p(d1[1]);
            mma16816((st & 1) ? zB : zA, w0,w1,w2,w3, ONE2, ONE2);
            uint32_t e0[2] = {0,0}, e1[2] = {0,0};
            mma16816h(e0, b0,b1,b2,b3, q0.x, q0.y);
            mma16816h(e1, b0,b1,b2,b3, q1.x, q1.y);
            uint32_t w4 = ex2p(e0[0]);
            uint32_t w5 = ex2p(e0[1]);
            uint32_t w6 = ex2p(e1[0]);
            uint32_t w7 = ex2p(e1[1]);
            mma16816((st & 1) ? zD : zC, w4,w5,w6,w7, ONE2, ONE2);
        }
        __syncthreads();
    }
    if (ktg == 0) {
        float* zp = g_Zpart + ((size_t)z*BH + bh)*SS + trow;
        zp[kg]      = zA[0] + zB[0];
        zp[8 + kg]  = zA[2] + zB[2];
        zp[16 + kg] = zC[0] + zD[0];
        zp[24 + kg] = zC[2] + zD[2];
    }
}

// ---------------- vnorm (transposed, coalesced): grid (SS/128, BH), 256 thr ----------------
__global__ __launch_bounds__(256) void vnormT_kernel()
{
    __shared__ __align__(16) __half sm[16][128];   // [e][t-permuted]
    int tid = threadIdx.x;
    int bh = blockIdx.y, t0 = blockIdx.x * 128;

    int t = tid >> 1, hf = tid & 1;                // row t, e-half
    int gi = bh*SS + t0 + t;
    float r = 1.0f / (g_Zpart[gi] + g_Zpart[(size_t)BH*SS + gi]);
    int tp = (t & ~15) + permpos(t & 15);
    const float4* vp = (const float4*)&g_v[(size_t)gi*HDD + hf*8];
    float4 v0 = vp[0], v1 = vp[1];
    sm[hf*8+0][tp] = __float2half(v0.x * r);
    sm[hf*8+1][tp] = __float2half(v0.y * r);
    sm[hf*8+2][tp] = __float2half(v0.z * r);
    sm[hf*8+3][tp] = __float2half(v0.w * r);
    sm[hf*8+4][tp] = __float2half(v1.x * r);
    sm[hf*8+5][tp] = __float2half(v1.y * r);
    sm[hf*8+6][tp] = __float2half(v1.z * r);
    sm[hf*8+7][tp] = __float2half(v1.w * r);
    __syncthreads();

    int e = tid >> 4, ch = tid & 15;               // 256 threads = 16 e x 16 chunks
    *(uint4*)(g_vt + (size_t)(bh*HDD + e)*SS + t0 + ch*8) = *(const uint4*)&sm[e][ch*8];
}

// ---------------- Pass B: partial attended; f16-D score MMAs ----------------
__global__ __launch_bounds__(128, 7) void attendW_kernel()
{
    __shared__ __align__(16) __half sk[2][2048];
    __shared__ __align__(16) __half sv[2][2048];
    int tid = threadIdx.x, w = tid >> 5, lane = tid & 31;
    int bh = blockIdx.y, z = blockIdx.z;
    int srow = blockIdx.x * 128 + w * 32;

    const __half* qb = g_q + (size_t)bh*SS*HDD;
    int qg = lane >> 2, qtg = lane & 3;
    uint2 s0a = *((const uint2*)(qb + (srow +      qg)*HDD) + qtg);
    uint2 s0c = *((const uint2*)(qb + (srow +  8 + qg)*HDD) + qtg);
    uint2 s1a = *((const uint2*)(qb + (srow + 16 + qg)*HDD) + qtg);
    uint2 s1c = *((const uint2*)(qb + (srow + 24 + qg)*HDD) + qtg);
    uint32_t a0 = s0a.x, a2 = s0a.y, a1 = s0c.x, a3 = s0c.y;
    uint32_t b0 = s1a.x, b2 = s1a.y, b1 = s1c.x, b3 = s1c.y;

    const __half* kb = g_k + (size_t)bh*SS*HDD + (size_t)z*(SS/2)*HDD;
    const __half* vt = g_vt + (size_t)bh*HDD*SS + (size_t)z*(SS/2);

    int kr0 = tid >> 1, kc0 = tid & 1;
    uint32_t kdst0 = frag_dst(kr0, kc0);
    uint32_t kdst1 = frag_dst(kr0 + 64, kc0);
    const __half* ksrc0 = kb + kr0*HDD + kc0*8;
    const __half* ksrc1 = kb + (kr0 + 64)*HDD + kc0*8;

    int ve0 = tid >> 4, vcv0 = tid & 15;
    int ve1 = (tid + 128) >> 4, vcv1 = tid & 15;
    uint32_t vdst0 = (uint32_t)((vcv0>>1)*512 + (ve0>>3)*256 + (ve0&7)*32 + (vcv0&1)*16);
    uint32_t vdst1 = (uint32_t)((vcv1>>1)*512 + (ve1>>3)*256 + (ve1&7)*32 + (vcv1&1)*16);
    const __half* vsrc0 = vt + (size_t)ve0*SS + vcv0*8;
    const __half* vsrc1 = vt + (size_t)ve1*SS + vcv1*8;

    uint32_t skb = smem_u32(sk), svb = smem_u32(sv);

    float o0[8] = {0,0,0,0,0,0,0,0};
    float o1[8] = {0,0,0,0,0,0,0,0};

    cpa16(skb + kdst0, ksrc0);
    cpa16(skb + kdst1, ksrc1);
    cpa16(svb + vdst0, vsrc0);
    cpa16(svb + vdst1, vsrc1);
    CP_COMMIT();

    const int NT = (SS/2)/128;
    for (int tile = 0; tile < NT; tile++) {
        int buf = tile & 1;
        if (tile + 1 < NT) {
            size_t koff = (size_t)(tile+1)*128*HDD;
            cpa16(skb + (buf^1)*4096 + kdst0, ksrc0 + koff);
            cpa16(skb + (buf^1)*4096 + kdst1, ksrc1 + koff);
            cpa16(svb + (buf^1)*4096 + vdst0, vsrc0 + (size_t)(tile+1)*128);
            cpa16(svb + (buf^1)*4096 + vdst1, vsrc1 + (size_t)(tile+1)*128);
            CP_COMMIT();
            CP_WAIT1();
        } else {
            CP_WAIT0();
        }
        __syncthreads();
        const char* kp = (const char*)sk + buf*4096 + lane*8;
        const char* vp = (const char*)sv + buf*4096 + lane*8;
        #pragma unroll
        for (int st = 0; st < 8; st++) {
            uint2 k0 = *(const uint2*)(kp + st*512);
            uint2 k1 = *(const uint2*)(kp + st*512 + 256);
            uint2 v0 = *(const uint2*)(vp + st*512);
            uint2 v1 = *(const uint2*)(vp + st*512 + 256);
            uint32_t d0[2] = {0,0}, d1[2] = {0,0};
            mma16816h(d0, a0,a1,a2,a3, k0.x, k0.y);
            mma16816h(d1, a0,a1,a2,a3, k1.x, k1.y);
            uint32_t w0 = ex2p(d0[0]);
            uint32_t w1 = ex2p(d0[1]);
            uint32_t w2 = ex2p(d1[0]);
            uint32_t w3 = ex2p(d1[1]);
            mma16816(o0,     w0,w1,w2,w3, v0.x, v0.y);
            mma16816(o0 + 4, w0,w1,w2,w3, v1.x, v1.y);
            uint32_t e0[2] = {0,0}, e1[2] = {0,0};
            mma16816h(e0, b0,b1,b2,b3, k0.x, k0.y);
            mma16816h(e1, b0,b1,b2,b3, k1.x, k1.y);
            uint32_t w4 = ex2p(e0[0]);
            uint32_t w5 = ex2p(e0[1]);
            uint32_t w6 = ex2p(e1[0]);
            uint32_t w7 = ex2p(e1[1]);
            mma16816(o1,     w4,w5,w6,w7, v0.x, v0.y);
            mma16816(o1 + 4, w4,w5,w6,w7, v1.x, v1.y);
        }
        __syncthreads();
    }

    int b = bh >> 2, h = bh & 3;
    float* att = g_att + (size_t)z*BB*SS*DD + (size_t)h*HDD;
    {
        float* dst0 = att + (size_t)(b*SS + srow + qg)*DD;
        float* dst1 = att + (size_t)(b*SS + srow + 8 + qg)*DD;
        *(float2*)(dst0 + 2*qtg)     = make_float2(o0[0], o0[1]);
        *(float2*)(dst1 + 2*qtg)     = make_float2(o0[2], o0[3]);
        *(float2*)(dst0 + 8 + 2*qtg) = make_float2(o0[4], o0[5]);
        *(float2*)(dst1 + 8 + 2*qtg) = make_float2(o0[6], o0[7]);
    }
    {
        float* dst0 = att + (size_t)(b*SS + srow + 16 + qg)*DD;
        float* dst1 = att + (size_t)(b*SS + srow + 24 + qg)*DD;
        *(float2*)(dst0 + 2*qtg)     = make_float2(o1[0], o1[1]);
        *(float2*)(dst1 + 2*qtg)     = make_float2(o1[2], o1[3]);
        *(float2*)(dst0 + 8 + 2*qtg) = make_float2(o1[4], o1[5]);
        *(float2*)(dst1 + 8 + 2*qtg) = make_float2(o1[6], o1[7]);
    }
}

// ---------------- out_proj via MMA: o = (att0+att1)@Wo + bo -> exp -> g_o + col partials ----------------
// grid 256, 128 thr; block = 64 rows.
__global__ __launch_bounds__(128) void out_projmma_kernel(
    const float* __restrict__ Wo, const float* __restrict__ bo)
{
    __shared__ __align__(16) char swo[64*160];     // Wo f16 B-frag layout [d][c permuted], 160B stride
    __shared__ __align__(16) char saf[8192];       // A-fragments
    __shared__ float sbo[64];
    __shared__ float sred[4][64];
    const float LOG2E = 1.4426950408889634f;

    int tid = threadIdx.x, w = tid >> 5, lane = tid & 31;
    int g = lane >> 2, tg = lane & 3;
    int row0 = blockIdx.x * 64;

    uint32_t swob = smem_u32(swo), safb = smem_u32(saf);

    // stage Wo -> f16 B-fragment layout: Wo[c][d] row-major (c = h*16+e)
    for (int i = tid; i < 4096; i += 128) {
        int c = i >> 6, d = i & 63;
        int off = d*160 + ((c >> 4) << 5) + permpos(c & 15)*2;
        *(__half*)(swo + off) = __float2half(Wo[i]);
    }
    if (tid < 64) sbo[tid] = bo[tid];

    // stage A: row r = tid>>1, c-half kh = tid&1; add the two attend partials, cvt f16, permute
    {
        int r = tid >> 1, kh = tid & 1;
        const float4* ar0 = (const float4*)(g_att + (size_t)(row0 + r)*DD + kh*32);
        const float4* ar1 = (const float4*)(g_att + (size_t)BB*SS*DD + (size_t)(row0 + r)*DD + kh*32);
        int wt = r >> 4, rr = r & 15;
        uint32_t base = safb + wt*2048 + ((rr>>3)&1)*256 + (rr&7)*32;
        #pragma unroll
        for (int gi2 = 0; gi2 < 2; gi2++) {
            float4 a0 = ar0[gi2*4+0], a1 = ar0[gi2*4+1], a2 = ar0[gi2*4+2], a3 = ar0[gi2*4+3];
            float4 c0 = ar1[gi2*4+0], c1 = ar1[gi2*4+1], c2 = ar1[gi2*4+2], c3 = ar1[gi2*4+3];
            float4 a = make_float4(a0.x+c0.x, a0.y+c0.y, a0.z+c0.z, a0.w+c0.w);
            float4 b = make_float4(a1.x+c1.x, a1.y+c1.y, a1.z+c1.z, a1.w+c1.w);
            float4 c = make_float4(a2.x+c2.x, a2.y+c2.y, a2.z+c2.z, a2.w+c2.w);
            float4 d = make_float4(a3.x+c3.x, a3.y+c3.y, a3.z+c3.z, a3.w+c3.w);
            int ks = kh*2 + gi2;
            sts128(base + ks*512,      pkh2(a.x,a.y), pkh2(c.x,c.y), pkh2(a.z,a.w), pkh2(c.z,c.w));
            sts128(base + ks*512 + 16, pkh2(b.x,b.y), pkh2(d.x,d.y), pkh2(b.z,b.w), pkh2(d.z,d.w));
        }
    }
    __syncthreads();

    uint32_t A0[4], A1[4], A2[4], A3[4];
    {
        uint32_t base = safb + w*2048 + lane*8;
        #pragma unroll
        for (int ks = 0; ks < 4; ks++) {
            uint2 p0, p1;
            asm volatile("ld.shared.v2.b32 {%0,%1}, [%2];" : "=r"(p0.x), "=r"(p0.y) : "r"(base + ks*512));
            asm volatile("ld.shared.v2.b32 {%0,%1}, [%2];" : "=r"(p1.x), "=r"(p1.y) : "r"(base + ks*512 + 256));
            A0[ks] = p0.x; A2[ks] = p0.y; A1[ks] = p1.x; A3[ks] = p1.y;
        }
    }

    int r0 = row0 + w*16 + g;
    int r1 = r0 + 8;

    #pragma unroll
    for (int nc = 0; nc < 8; nc++) {
        float d[4] = {0.f, 0.f, 0.f, 0.f};
        uint32_t brow = swob + (nc*8 + g)*160 + tg*8;
        #pragma unroll
        for (int ks = 0; ks < 4; ks++) {
            uint2 bfr;
            asm volatile("ld.shared.v2.b32 {%0,%1}, [%2];" : "=r"(bfr.x), "=r"(bfr.y) : "r"(brow + ks*32));
            mma16816(d, A0[ks], A1[ks], A2[ks], A3[ks], bfr.x, bfr.y);
        }
        int col = nc*8 + 2*tg;
        float2 bia = *(const float2*)&sbo[col];
        float ev00 = ex2f((d[0] + bia.x) * LOG2E);
        float ev01 = ex2f((d[1] + bia.y) * LOG2E);
        float ev10 = ex2f((d[2] + bia.x) * LOG2E);
        float ev11 = ex2f((d[3] + bia.y) * LOG2E);
        *(float2*)&g_o[(size_t)r0*DD + col] = make_float2(ev00, ev01);
        *(float2*)&g_o[(size_t)r1*DD + col] = make_float2(ev10, ev11);
        // column partial over this warp's 16 rows: reduce across g (lanes stride 4)
        float c0 = ev00 + ev10;
        float c1 = ev01 + ev11;
        c0 += __shfl_xor_sync(0xFFFFFFFFu, c0, 4);
        c0 += __shfl_xor_sync(0xFFFFFFFFu, c0, 8);
        c0 += __shfl_xor_sync(0xFFFFFFFFu, c0, 16);
        c1 += __shfl_xor_sync(0xFFFFFFFFu, c1, 4);
        c1 += __shfl_xor_sync(0xFFFFFFFFu, c1, 8);
        c1 += __shfl_xor_sync(0xFFFFFFFFu, c1, 16);
        if (g == 0) {
            sred[w][col]     = c0;
            sred[w][col + 1] = c1;
        }
    }
    __syncthreads();
    if (tid < 64)
        g_Zop[blockIdx.x*64 + tid] = sred[0][tid] + sred[1][tid] + sred[2][tid] + sred[3][tid];
}

// ---------------- zsum: 64 block-partials per batch ----------------
__global__ __launch_bounds__(256) void zsum_kernel()
{
    __shared__ float red[4][64];
    int b = blockIdx.x;
    int d = threadIdx.x & 63, cg = threadIdx.x >> 6;
    float s = 0.f;
    for (int c = cg; c < 64; c += 4)
        s += g_Zop[(b*64 + c)*64 + d];
    red[cg][d] = s;
    __syncthreads();
    if (cg == 0)
        g_Zo[b*64 + d] = red[0][d] + red[1][d] + red[2][d] + red[3][d];
}

// ---------------- final ----------------
__global__ __launch_bounds__(256) void final_scale_kernel(float* __restrict__ out)
{
    int idx = blockIdx.x * 256 + threadIdx.x;
    int row = idx >> 4;
    int b = row >> 12;
    int d4 = idx & 15;
    float4 e = ((const float4*)g_o)[idx];
    float4 zz = ((const float4*)g_Zo)[b*16 + d4];
    float4 o;
    o.x = __fdividef(e.x, zz.x);
    o.y = __fdividef(e.y, zz.y);
    o.z = __fdividef(e.z, zz.z);
    o.w = __fdividef(e.w, zz.w);
    ((float4*)out)[idx] = o;
}

// ---------------- launch ----------------
extern "C" void kernel_launch(void* const* d_in, const int* in_sizes, int n_in,
                              void* d_out, int out_size)
{
    const float* x  = (const float*)d_in[0];
    const float* Wq = (const float*)d_in[1];
    const float* bq = (const float*)d_in[2];
    const float* Wk = (const float*)d_in[3];
    const float* bk = (const float*)d_in[4];
    const float* Wv = (const float*)d_in[5];
    const float* bv = (const float*)d_in[6];
    const float* Wo = (const float*)d_in[7];
    const float* bo = (const float*)d_in[8];
    float* out = (float*)d_out;

    const float qscale = 0.25f * 1.4426950408889634f;  // 1/sqrt(HD) * log2(e)

    wtprep_kernel<<<192, 64>>>(Wq, Wk, Wv);
    projmma_kernel<<<256, 128>>>(x, bq, bk, bv, qscale);

    colsumW_kernel<<<dim3(32, BH, 2), 128>>>();
    vnormT_kernel<<<dim3(SS/128, BH), 256>>>();
    attendW_kernel<<<dim3(32, BH, 2), 128>>>();

    out_projmma_kernel<<<256, 128>>>(Wo, bo);
    zsum_kernel<<<BB, 256>>>();
    final_scale_kernel<<<(BB*SS*DD/4)/256, 256>>>(out);
}